// round 11
// baseline (speedup 1.0000x reference)
#include <cuda_runtime.h>
#include <cuda_bf16.h>
#include <cstdint>
#include <cstddef>

// ---------------------------------------------------------------------------
// Problem constants
// ---------------------------------------------------------------------------
#define VV 50257
#define DD 512
#define HH 8
#define KK 64
#define FF 2048
#define EE 4
#define LL 128
#define BB 8
#define SS 512
#define NT 4096   // B*S tokens

// ---------------------------------------------------------------------------
// Scratch (device globals -- no runtime allocation allowed)
// ---------------------------------------------------------------------------
__device__ float g_X  [NT * DD];
__device__ float g_V  [NT * DD];
__device__ float g_O  [NT * DD];
__device__ float g_X2 [NT * DD];
__device__ float g_T1 [NT * FF];
__device__ float g_H  [NT * DD];
__device__ float g_AGG[NT * DD];
__device__ float g_Z0 [NT * DD];
__device__ float g_SC [BB * HH * SS * SS];     // 64 MB (base attention only)
__device__ float g_LST[NT * LL];
__device__ int   g_IDX[NT];
__device__ float g_XE  [EE * NT * DD];
__device__ float g_VE  [EE * NT * DD];
__device__ float g_OUTE[EE * NT * DD];
__device__ float g_SCR [4 * NT * DD];          // base QKV / split-K partials
__device__ float g_WQKV[3 * DD * DD];

// bf16 split buffers
__device__ __nv_bfloat16 g_Qhi[EE * NT * DD];
__device__ __nv_bfloat16 g_Qlo[EE * NT * DD];
__device__ __nv_bfloat16 g_Khi[EE * NT * DD];
__device__ __nv_bfloat16 g_Klo[EE * NT * DD];
__device__ __nv_bfloat16 g_VThi[EE * NT * DD];
__device__ __nv_bfloat16 g_VTlo[EE * NT * DD];
__device__ __nv_bfloat16 g_Phi[(long)EE * BB * HH * SS * SS];
__device__ __nv_bfloat16 g_Plo[(long)EE * BB * HH * SS * SS];
#define ABMAX ((long)EE * NT * FF)
__device__ __nv_bfloat16 g_ABhi[ABMAX];
__device__ __nv_bfloat16 g_ABlo[ABMAX];
__device__ __nv_bfloat16 g_CBhi[ABMAX];
__device__ __nv_bfloat16 g_CBlo[ABMAX];

// transposed+split weights, packed offsets (elements)
#define OFF_EQ 0L
#define OFF_EK 1048576L
#define OFF_EV 2097152L
#define OFF_EO 3145728L
#define OFF_E1 4194304L
#define OFF_E2 8388608L
#define OFF_AQ 12582912L
#define OFF_AK 12845056L
#define OFF_AV 13107200L
#define OFF_AO 13369344L
#define OFF_LS 13631488L
#define WT_TOTAL 13893632L
__device__ __nv_bfloat16 g_WThi[WT_TOTAL];
__device__ __nv_bfloat16 g_WTlo[WT_TOTAL];

// ---------------------------------------------------------------------------
// Embedding gathers
// ---------------------------------------------------------------------------
__global__ void embed_gather(const int* __restrict__ ids,
                             const float* __restrict__ emb,
                             float* __restrict__ X)
{
    int tok = blockIdx.x;
    int id = ids[tok];
    const float4* src = (const float4*)(emb + (size_t)id * DD);
    float4* dst = (float4*)(X + (size_t)tok * DD);
    dst[threadIdx.x] = src[threadIdx.x];
}

__global__ void embed_gather_e(const int* __restrict__ ids,
                               const int* __restrict__ route,
                               const float* __restrict__ emb,
                               float* __restrict__ XE)
{
    int e = blockIdx.y;
    int tok = blockIdx.x;
    int id = (route[tok] == e) ? ids[tok] : 0;
    const float4* src = (const float4*)(emb + ((size_t)e * VV + id) * DD);
    float4* dst = (float4*)(XE + ((size_t)e * NT + tok) * DD);
    dst[threadIdx.x] = src[threadIdx.x];
}

// ---------------------------------------------------------------------------
// Split fp32 -> (bf16 hi, bf16 lo)
// ---------------------------------------------------------------------------
__global__ void split_bf(const float* __restrict__ x,
                         __nv_bfloat16* __restrict__ hi,
                         __nv_bfloat16* __restrict__ lo, long n)
{
    long i = ((long)blockIdx.x * blockDim.x + threadIdx.x) * 4;
    if (i >= n) return;
    float4 v = *(const float4*)(x + i);
    __nv_bfloat16 h0 = __float2bfloat16(v.x);
    __nv_bfloat16 h1 = __float2bfloat16(v.y);
    __nv_bfloat16 h2 = __float2bfloat16(v.z);
    __nv_bfloat16 h3 = __float2bfloat16(v.w);
    *(__nv_bfloat162*)(hi + i)     = __nv_bfloat162(h0, h1);
    *(__nv_bfloat162*)(hi + i + 2) = __nv_bfloat162(h2, h3);
    *(__nv_bfloat162*)(lo + i)     = __nv_bfloat162(
        __float2bfloat16(v.x - __bfloat162float(h0)),
        __float2bfloat16(v.y - __bfloat162float(h1)));
    *(__nv_bfloat162*)(lo + i + 2) = __nv_bfloat162(
        __float2bfloat16(v.z - __bfloat162float(h2)),
        __float2bfloat16(v.w - __bfloat162float(h3)));
}

// ---------------------------------------------------------------------------
// Transpose + split weights: W[Kd,N] (z-strided) -> T[N,Kd] hi/lo
// ---------------------------------------------------------------------------
__global__ void tsplit(const float* __restrict__ W,
                       __nv_bfloat16* __restrict__ Thi,
                       __nv_bfloat16* __restrict__ Tlo,
                       int Kd, int N, long sW, long sT)
{
    __shared__ float t[32][33];
    W   += (long)blockIdx.z * sW;
    Thi += (long)blockIdx.z * sT;
    Tlo += (long)blockIdx.z * sT;
    int n0 = blockIdx.x * 32, k0 = blockIdx.y * 32;
    int tx = threadIdx.x, ty = threadIdx.y;
#pragma unroll
    for (int i = 0; i < 32; i += 8)
        t[ty + i][tx] = W[(long)(k0 + ty + i) * N + n0 + tx];
    __syncthreads();
#pragma unroll
    for (int i = 0; i < 32; i += 8) {
        float v = t[tx][ty + i];
        __nv_bfloat16 h = __float2bfloat16(v);
        long idx = (long)(n0 + ty + i) * Kd + k0 + tx;
        Thi[idx] = h;
        Tlo[idx] = __float2bfloat16(v - __bfloat162float(h));
    }
}

// ---------------------------------------------------------------------------
// Transpose + split V per (e,b,h): V[s, h*64+k] -> VT[z][k][s]
// grid (SS/32, KK/32, Z) ; Z = e*64 + b*8 + h
// ---------------------------------------------------------------------------
__global__ void vtsplit(const float* __restrict__ V,
                        __nv_bfloat16* __restrict__ Thi,
                        __nv_bfloat16* __restrict__ Tlo)
{
    __shared__ float t[32][33];
    int z = blockIdx.z, e = z >> 6, bh = z & 63, b = bh >> 3, h = bh & 7;
    int s0 = blockIdx.x * 32, k0 = blockIdx.y * 32;
    int tx = threadIdx.x, ty = threadIdx.y;
#pragma unroll
    for (int i = 0; i < 32; i += 8)
        t[ty + i][tx] = V[((long)e * NT + b * SS + s0 + ty + i) * DD + h * KK + k0 + tx];
    __syncthreads();
#pragma unroll
    for (int i = 0; i < 32; i += 8) {
        float v = t[tx][ty + i];
        __nv_bfloat16 hh = __float2bfloat16(v);
        long idx = ((long)z * KK + k0 + ty + i) * SS + s0 + tx;
        Thi[idx] = hh;
        Tlo[idx] = __float2bfloat16(v - __bfloat162float(hh));
    }
}

// ---------------------------------------------------------------------------
// Pack wq,wk,wv into one contiguous buffer
// ---------------------------------------------------------------------------
__global__ void pack3(const float* __restrict__ a, const float* __restrict__ b,
                      const float* __restrict__ c, float* __restrict__ dst)
{
    int i = blockIdx.x * 256 + threadIdx.x;                // float4 units
    const int per = DD * DD / 4;
    const float* s = (i < per) ? a : (i < 2 * per) ? b : c;
    int off = i % per;
    ((float4*)dst)[i] = ((const float4*)s)[off];
}

// ---------------------------------------------------------------------------
// MMA helpers
// ---------------------------------------------------------------------------
__device__ __forceinline__ void mma16816(float* c, const uint32_t* a, const uint32_t* b)
{
    asm volatile(
        "mma.sync.aligned.m16n8k16.row.col.f32.bf16.bf16.f32 "
        "{%0,%1,%2,%3}, {%4,%5,%6,%7}, {%8,%9}, {%0,%1,%2,%3};"
        : "+f"(c[0]), "+f"(c[1]), "+f"(c[2]), "+f"(c[3])
        : "r"(a[0]), "r"(a[1]), "r"(a[2]), "r"(a[3]), "r"(b[0]), "r"(b[1]));
}

__device__ __forceinline__ void ldsm4(uint32_t* r, uint32_t addr)
{
    asm volatile("ldmatrix.sync.aligned.m8n8.x4.shared.b16 {%0,%1,%2,%3}, [%4];"
                 : "=r"(r[0]), "=r"(r[1]), "=r"(r[2]), "=r"(r[3]) : "r"(addr));
}

__device__ __forceinline__ void split_store2(__nv_bfloat16* hi, __nv_bfloat16* lo,
                                             float x0, float x1)
{
    __nv_bfloat16 h0 = __float2bfloat16(x0);
    __nv_bfloat16 h1 = __float2bfloat16(x1);
    *(__nv_bfloat162*)hi = __nv_bfloat162(h0, h1);
    *(__nv_bfloat162*)lo = __nv_bfloat162(
        __float2bfloat16(x0 - __bfloat162float(h0)),
        __float2bfloat16(x1 - __bfloat162float(h1)));
}

// ---------------------------------------------------------------------------
// Split-bf16 tensor-core GEMM: C = (Ahi+Alo)[M,K] @ (Bhi+Blo)[N,K]^T
// Outputs: fp32 C (if non-null) and/or split bf16 Chi/Clo (if non-null).
// ---------------------------------------------------------------------------
#define HG_SMEM 81920

__global__ __launch_bounds__(256)
void hgemm_split(const __nv_bfloat16* __restrict__ Ahi0, const __nv_bfloat16* __restrict__ Alo0,
                 const __nv_bfloat16* __restrict__ Bhi0, const __nv_bfloat16* __restrict__ Blo0,
                 const float* __restrict__ bias, float* __restrict__ C,
                 __nv_bfloat16* __restrict__ Chi, __nv_bfloat16* __restrict__ Clo,
                 int M, int N, int Kd, int flags,
                 long sA, long sB, long sBias, long sC)
{
    extern __shared__ char sm[];
    const __nv_bfloat16* gA[2] = { Ahi0 + (long)blockIdx.z * sA, Alo0 + (long)blockIdx.z * sA };
    const __nv_bfloat16* gB[2] = { Bhi0 + (long)blockIdx.z * sB, Blo0 + (long)blockIdx.z * sB };
    if (bias) bias += (long)blockIdx.z * sBias;
    if (C)   C   += (long)blockIdx.z * sC;
    if (Chi) { Chi += (long)blockIdx.z * sC; Clo += (long)blockIdx.z * sC; }

    int tid = threadIdx.x, lane = tid & 31, wid = tid >> 5;
    int m0 = blockIdx.y * 128, n0 = blockIdx.x * 128;
    int m0w = (wid >> 2) * 64, n0w = (wid & 3) * 32;

    int grow = tid >> 1;
    int gseg = (tid & 1) * 16;

    uint32_t smb = (uint32_t)__cvta_generic_to_shared(sm);

    float acc[4][4][4];
#pragma unroll
    for (int i = 0; i < 4; i++)
#pragma unroll
        for (int j = 0; j < 4; j++)
#pragma unroll
            for (int r = 0; r < 4; r++) acc[i][j][r] = 0.f;

    int r16 = lane & 15, kq = lane >> 4;
    uint32_t aoff = (uint32_t)((m0w + r16) * 80 + kq * 16);
    uint32_t boff = (uint32_t)((n0w + r16) * 80 + kq * 16);
    uint32_t soff = (uint32_t)(grow * 80 + gseg * 2);

    int nch = Kd >> 5;

#pragma unroll
    for (int h = 0; h < 2; h++) {
        const uint4* pa = (const uint4*)(gA[h] + (long)(m0 + grow) * Kd + gseg);
        const uint4* pb = (const uint4*)(gB[h] + (long)(n0 + grow) * Kd + gseg);
        uint4 va0 = pa[0], va1 = pa[1];
        uint4 vb0 = pb[0], vb1 = pb[1];
        *(uint4*)(sm + h * 10240 + soff)              = va0;
        *(uint4*)(sm + h * 10240 + soff + 16)         = va1;
        *(uint4*)(sm + 40960 + h * 10240 + soff)      = vb0;
        *(uint4*)(sm + 40960 + h * 10240 + soff + 16) = vb1;
    }
    __syncthreads();

    uint4 pre[2][2][2];
    int buf = 0;
    for (int ch = 0; ch < nch; ch++) {
        if (ch + 1 < nch) {
            long k0 = (long)(ch + 1) * 32;
#pragma unroll
            for (int h = 0; h < 2; h++) {
                const uint4* pa = (const uint4*)(gA[h] + (long)(m0 + grow) * Kd + k0 + gseg);
                const uint4* pb = (const uint4*)(gB[h] + (long)(n0 + grow) * Kd + k0 + gseg);
                pre[0][h][0] = pa[0]; pre[0][h][1] = pa[1];
                pre[1][h][0] = pb[0]; pre[1][h][1] = pb[1];
            }
        }
#pragma unroll
        for (int ks = 0; ks < 2; ks++) {
            uint32_t afr[2][4][4];
            uint32_t bfr[2][4][2];
#pragma unroll
            for (int h = 0; h < 2; h++) {
                uint32_t ab = smb + (buf * 2 + h) * 10240 + aoff + ks * 32;
#pragma unroll
                for (int i = 0; i < 4; i++)
                    ldsm4(afr[h][i], ab + i * 16 * 80);
                uint32_t bb = smb + 40960 + (buf * 2 + h) * 10240 + boff + ks * 32;
#pragma unroll
                for (int j2 = 0; j2 < 2; j2++) {
                    uint32_t t[4];
                    ldsm4(t, bb + j2 * 16 * 80);
                    bfr[h][2 * j2][0]     = t[0]; bfr[h][2 * j2][1]     = t[2];
                    bfr[h][2 * j2 + 1][0] = t[1]; bfr[h][2 * j2 + 1][1] = t[3];
                }
            }
#pragma unroll
            for (int i = 0; i < 4; i++)
#pragma unroll
                for (int j = 0; j < 4; j++) {
                    mma16816(acc[i][j], afr[0][i], bfr[0][j]);
                    mma16816(acc[i][j], afr[0][i], bfr[1][j]);
                    mma16816(acc[i][j], afr[1][i], bfr[0][j]);
                }
        }
        if (ch + 1 < nch) {
            buf ^= 1;
#pragma unroll
            for (int h = 0; h < 2; h++) {
                *(uint4*)(sm + (buf * 2 + h) * 10240 + soff)              = pre[0][h][0];
                *(uint4*)(sm + (buf * 2 + h) * 10240 + soff + 16)         = pre[0][h][1];
                *(uint4*)(sm + 40960 + (buf * 2 + h) * 10240 + soff)      = pre[1][h][0];
                *(uint4*)(sm + 40960 + (buf * 2 + h) * 10240 + soff + 16) = pre[1][h][1];
            }
            __syncthreads();
        }
    }

    int rl = lane >> 2;
    int cl = (lane & 3) * 2;
#pragma unroll
    for (int i = 0; i < 4; i++) {
        int row = m0 + m0w + i * 16 + rl;
#pragma unroll
        for (int j = 0; j < 4; j++) {
            int col = n0 + n0w + j * 8 + cl;
            float x0 = acc[i][j][0], x1 = acc[i][j][1];
            float x2 = acc[i][j][2], x3 = acc[i][j][3];
            if (flags & 1) {
                float b0 = bias[col], b1 = bias[col + 1];
                x0 += b0; x1 += b1; x2 += b0; x3 += b1;
            }
            if (C) {
                *(float2*)(C + (long)row * N + col)       = make_float2(x0, x1);
                *(float2*)(C + (long)(row + 8) * N + col) = make_float2(x2, x3);
            }
            if (Chi) {
                split_store2(Chi + (long)row * N + col, Clo + (long)row * N + col, x0, x1);
                split_store2(Chi + (long)(row + 8) * N + col, Clo + (long)(row + 8) * N + col, x2, x3);
            }
        }
    }
}

// ---------------------------------------------------------------------------
// TC attention scores: P(raw) = (1/8) Q K^T per (e,b,h), split-bf16 in/out.
// grid (4 s-tiles, 4 q-tiles, Z=e*64+bh), 256 threads.
// ---------------------------------------------------------------------------
#define TCS_SMEM (4 * 128 * 72 * 2)

__global__ __launch_bounds__(256)
void tc_scores(const __nv_bfloat16* __restrict__ Qhi, const __nv_bfloat16* __restrict__ Qlo,
               const __nv_bfloat16* __restrict__ Khi, const __nv_bfloat16* __restrict__ Klo,
               __nv_bfloat16* __restrict__ Phi, __nv_bfloat16* __restrict__ Plo)
{
    extern __shared__ char sm[];
    int z = blockIdx.z, e = z >> 6, bh = z & 63, b = bh >> 3, h = bh & 7;
    int q0 = blockIdx.y * 128, s0 = blockIdx.x * 128;
    int tid = threadIdx.x, lane = tid & 31, wid = tid >> 5;

    long qb = ((long)e * NT + b * SS + q0) * DD + h * KK;
    long kb = ((long)e * NT + b * SS + s0) * DD + h * KK;

    int row = tid >> 1, hf = (tid & 1) * 32;
    {
        long ga = qb + (long)row * DD + hf;
        long gk = kb + (long)row * DD + hf;
        char* sp = sm + (row * 72 + hf) * 2;
        // full 32 elems (64 bytes) per thread for each of the 4 operands
#pragma unroll
        for (int u = 0; u < 4; u++) {
            *(uint4*)(sp + u * 16)         = *(const uint4*)(Qhi + ga + u * 8);
            *(uint4*)(sp + 18432 + u * 16) = *(const uint4*)(Qlo + ga + u * 8);
            *(uint4*)(sp + 36864 + u * 16) = *(const uint4*)(Khi + gk + u * 8);
            *(uint4*)(sp + 55296 + u * 16) = *(const uint4*)(Klo + gk + u * 8);
        }
    }
    __syncthreads();

    uint32_t smb = (uint32_t)__cvta_generic_to_shared(sm);
    int m0w = (wid >> 2) * 64, n0w = (wid & 3) * 32;
    int r16 = lane & 15, kq = lane >> 4;

    float acc[4][4][4];
#pragma unroll
    for (int i = 0; i < 4; i++)
#pragma unroll
        for (int j = 0; j < 4; j++)
#pragma unroll
            for (int r = 0; r < 4; r++) acc[i][j][r] = 0.f;

#pragma unroll
    for (int ks = 0; ks < 4; ks++) {
        uint32_t afr[2][4][4], bfr[2][4][2];
#pragma unroll
        for (int hh = 0; hh < 2; hh++) {
            uint32_t ab = smb + hh * 18432 + (m0w + r16) * 144 + kq * 16 + ks * 32;
#pragma unroll
            for (int i = 0; i < 4; i++)
                ldsm4(afr[hh][i], ab + i * 16 * 144);
            uint32_t bb = smb + 36864 + hh * 18432 + (n0w + r16) * 144 + kq * 16 + ks * 32;
#pragma unroll
            for (int j2 = 0; j2 < 2; j2++) {
                uint32_t t[4];
                ldsm4(t, bb + j2 * 16 * 144);
                bfr[hh][2 * j2][0]     = t[0]; bfr[hh][2 * j2][1]     = t[2];
                bfr[hh][2 * j2 + 1][0] = t[1]; bfr[hh][2 * j2 + 1][1] = t[3];
            }
        }
#pragma unroll
        for (int i = 0; i < 4; i++)
#pragma unroll
            for (int j = 0; j < 4; j++) {
                mma16816(acc[i][j], afr[0][i], bfr[0][j]);
                mma16816(acc[i][j], afr[0][i], bfr[1][j]);
                mma16816(acc[i][j], afr[1][i], bfr[0][j]);
            }
    }

    int rl = lane >> 2, cl = (lane & 3) * 2;
    long pb = (long)z * SS * SS;
#pragma unroll
    for (int i = 0; i < 4; i++) {
        int r0 = q0 + m0w + i * 16 + rl;
#pragma unroll
        for (int j = 0; j < 4; j++) {
            int c0 = s0 + n0w + j * 8 + cl;
            long o0 = pb + (long)r0 * SS + c0;
            long o1 = pb + (long)(r0 + 8) * SS + c0;
            split_store2(Phi + o0, Plo + o0, acc[i][j][0] * 0.125f, acc[i][j][1] * 0.125f);
            split_store2(Phi + o1, Plo + o1, acc[i][j][2] * 0.125f, acc[i][j][3] * 0.125f);
        }
    }
}

// ---------------------------------------------------------------------------
// Softmax on split rows (in place): read hi+lo, softmax, write split probs.
// One warp per 512-row.
// ---------------------------------------------------------------------------
__global__ void softmax_split(__nv_bfloat16* __restrict__ Phi,
                              __nv_bfloat16* __restrict__ Plo)
{
    long gw = ((long)blockIdx.x * blockDim.x + threadIdx.x) >> 5;
    int lane = threadIdx.x & 31;
    __nv_bfloat16* ph = Phi + gw * SS + lane * 16;
    __nv_bfloat16* pl = Plo + gw * SS + lane * 16;

    float x[16];
#pragma unroll
    for (int t = 0; t < 8; t++) {
        __nv_bfloat162 a = ((const __nv_bfloat162*)ph)[t];
        __nv_bfloat162 b = ((const __nv_bfloat162*)pl)[t];
        x[2 * t]     = __bfloat162float(a.x) + __bfloat162float(b.x);
        x[2 * t + 1] = __bfloat162float(a.y) + __bfloat162float(b.y);
    }
    float mx = -1e30f;
#pragma unroll
    for (int t = 0; t < 16; t++) mx = fmaxf(mx, x[t]);
#pragma unroll
    for (int o = 16; o; o >>= 1) mx = fmaxf(mx, __shfl_xor_sync(0xffffffffu, mx, o));
    float sum = 0.f;
#pragma unroll
    for (int t = 0; t < 16; t++) { x[t] = expf(x[t] - mx); sum += x[t]; }
#pragma unroll
    for (int o = 16; o; o >>= 1) sum += __shfl_xor_sync(0xffffffffu, sum, o);
    float inv = 1.f / sum;
#pragma unroll
    for (int t = 0; t < 8; t++) {
        float x0 = x[2 * t] * inv, x1 = x[2 * t + 1] * inv;
        __nv_bfloat16 h0 = __float2bfloat16(x0);
        __nv_bfloat16 h1 = __float2bfloat16(x1);
        ((__nv_bfloat162*)ph)[t] = __nv_bfloat162(h0, h1);
        ((__nv_bfloat162*)pl)[t] = __nv_bfloat162(
            __float2bfloat16(x0 - __bfloat162float(h0)),
            __float2bfloat16(x1 - __bfloat162float(h1)));
    }
}

// ---------------------------------------------------------------------------
// TC AV: O[q, k] = sum_s P[q,s] VT[k,s], split in, split out.
// grid (4 q-tiles, 1, Z=e*64+bh), 256 threads.
// ---------------------------------------------------------------------------
#define TAV_SMEM (2 * 128 * 72 * 2 + 2 * 64 * 72 * 2)

__global__ __launch_bounds__(256)
void tc_av(const __nv_bfloat16* __restrict__ Phi, const __nv_bfloat16* __restrict__ Plo,
           const __nv_bfloat16* __restrict__ VThi, const __nv_bfloat16* __restrict__ VTlo,
           __nv_bfloat16* __restrict__ Ohi, __nv_bfloat16* __restrict__ Olo)
{
    extern __shared__ char sm[];
    int z = blockIdx.z, e = z >> 6, bh = z & 63, b = bh >> 3, h = bh & 7;
    int q0 = blockIdx.x * 128;
    int tid = threadIdx.x, lane = tid & 31, wid = tid >> 5;

    long pb = (long)z * SS * SS + (long)q0 * SS;
    long vb = (long)z * KK * SS;

    int m0w = (wid & 3) * 32, n0w = (wid >> 2) * 32;
    int r16 = lane & 15, kq = lane >> 4;

    int arow = tid >> 1, ahalf = (tid & 1) * 32;
    int brow = tid >> 2, bq = (tid & 3) * 16;

    uint32_t smb = (uint32_t)__cvta_generic_to_shared(sm);

    float acc[2][4][4];
#pragma unroll
    for (int i = 0; i < 2; i++)
#pragma unroll
        for (int j = 0; j < 4; j++)
#pragma unroll
            for (int r = 0; r < 4; r++) acc[i][j][r] = 0.f;

    for (int ch = 0; ch < 8; ch++) {
        __syncthreads();
        {
            long ga = pb + (long)arow * SS + ch * 64 + ahalf;
            char* sp = sm + (arow * 72 + ahalf) * 2;
            // full 32 elems (64 bytes) per thread for P hi and lo
#pragma unroll
            for (int u = 0; u < 4; u++) {
                *(uint4*)(sp + u * 16)         = *(const uint4*)(Phi + ga + u * 8);
                *(uint4*)(sp + 18432 + u * 16) = *(const uint4*)(Plo + ga + u * 8);
            }
            long gv = vb + (long)brow * SS + ch * 64 + bq;
            char* sq = sm + 36864 + (brow * 72 + bq) * 2;
            uint4 v;
            v = *(const uint4*)(VThi + gv);     *(uint4*)(sq)             = v;
            v = *(const uint4*)(VThi + gv + 8); *(uint4*)(sq + 16)        = v;
            v = *(const uint4*)(VTlo + gv);     *(uint4*)(sq + 9216)      = v;
            v = *(const uint4*)(VTlo + gv + 8); *(uint4*)(sq + 9216 + 16) = v;
        }
        __syncthreads();

#pragma unroll
        for (int ks = 0; ks < 4; ks++) {
            uint32_t afr[2][2][4], bfr[2][4][2];
#pragma unroll
            for (int hh = 0; hh < 2; hh++) {
                uint32_t ab = smb + hh * 18432 + (m0w + r16) * 144 + kq * 16 + ks * 32;
#pragma unroll
                for (int i = 0; i < 2; i++)
                    ldsm4(afr[hh][i], ab + i * 16 * 144);
                uint32_t bb = smb + 36864 + hh * 9216 + (n0w + r16) * 144 + kq * 16 + ks * 32;
#pragma unroll
                for (int j2 = 0; j2 < 2; j2++) {
                    uint32_t t[4];
                    ldsm4(t, bb + j2 * 16 * 144);
                    bfr[hh][2 * j2][0]     = t[0]; bfr[hh][2 * j2][1]     = t[2];
                    bfr[hh][2 * j2 + 1][0] = t[1]; bfr[hh][2 * j2 + 1][1] = t[3];
                }
            }
#pragma unroll
            for (int i = 0; i < 2; i++)
#pragma unroll
                for (int j = 0; j < 4; j++) {
                    mma16816(acc[i][j], afr[0][i], bfr[0][j]);
                    mma16816(acc[i][j], afr[0][i], bfr[1][j]);
                    mma16816(acc[i][j], afr[1][i], bfr[0][j]);
                }
        }
    }

    int rl = lane >> 2, cl = (lane & 3) * 2;
#pragma unroll
    for (int i = 0; i < 2; i++) {
        int r0 = q0 + m0w + i * 16 + rl;
#pragma unroll
        for (int j = 0; j < 4; j++) {
            int c0 = n0w + j * 8 + cl;
            long o0 = ((long)e * NT + b * SS + r0) * DD + h * KK + c0;
            long o1 = ((long)e * NT + b * SS + r0 + 8) * DD + h * KK + c0;
            split_store2(Ohi + o0, Olo + o0, acc[i][j][0], acc[i][j][1]);
            split_store2(Ohi + o1, Olo + o1, acc[i][j][2], acc[i][j][3]);
        }
    }
}

// ---------------------------------------------------------------------------
// fp32 double-buffered SGEMM (base block), with lda + z-batching
// ---------------------------------------------------------------------------
__global__ __launch_bounds__(256)
void sgemm_db(const float* __restrict__ A, const float* __restrict__ B,
              const float* __restrict__ bias, float* __restrict__ C,
              int M, int N, int Kd, int lda, int flags,
              long sA, long sB, long sBias, long sC)
{
    A += (long)blockIdx.z * sA;
    B += (long)blockIdx.z * sB;
    if (bias) bias += (long)blockIdx.z * sBias;
    C += (long)blockIdx.z * sC;

    const int AP = 132;
    __shared__ float As[2][16][AP];
    __shared__ float Bs[2][16][128];

    int tid = threadIdx.x;
    int wid = tid >> 5, lane = tid & 31;
    int wm = wid & 3, wn = wid >> 2;
    int lm = lane & 3, ln = lane >> 2;
    int m0 = blockIdx.y * 128, n0 = blockIdx.x * 128;

    int rowA = tid >> 2, colA = (tid & 3) << 2;
    int rowB = tid >> 5, colB = lane << 2;

    const float* Ap = A + (long)(m0 + rowA) * lda + colA;
    const float* Bp = B + (long)rowB * N + n0 + colB;

    float acc[8][8];
#pragma unroll
    for (int i = 0; i < 8; i++)
#pragma unroll
        for (int j = 0; j < 8; j++) acc[i][j] = 0.f;

    int nch = Kd >> 4;

    float4 ra0 = *(const float4*)(Ap);
    float4 ra1 = *(const float4*)(Ap + (long)64 * lda);
    float4 rb0 = *(const float4*)(Bp);
    float4 rb1 = *(const float4*)(Bp + (long)8 * N);

    As[0][colA + 0][rowA] = ra0.x; As[0][colA + 1][rowA] = ra0.y;
    As[0][colA + 2][rowA] = ra0.z; As[0][colA + 3][rowA] = ra0.w;
    As[0][colA + 0][rowA + 64] = ra1.x; As[0][colA + 1][rowA + 64] = ra1.y;
    As[0][colA + 2][rowA + 64] = ra1.z; As[0][colA + 3][rowA + 64] = ra1.w;
    *(float4*)&Bs[0][rowB][colB]     = rb0;
    *(float4*)&Bs[0][rowB + 8][colB] = rb1;
    __syncthreads();

    int buf = 0;
    for (int ch = 0; ch < nch; ch++) {
        if (ch + 1 < nch) {
            const float* Ap2 = Ap + (long)(ch + 1) * 16;
            const float* Bp2 = Bp + (long)(ch + 1) * 16 * N;
            ra0 = *(const float4*)(Ap2);
            ra1 = *(const float4*)(Ap2 + (long)64 * lda);
            rb0 = *(const float4*)(Bp2);
            rb1 = *(const float4*)(Bp2 + (long)8 * N);
        }
#pragma unroll
        for (int kk = 0; kk < 16; kk++) {
            float a[8], b[8];
            *(float4*)(a)     = *(const float4*)&As[buf][kk][wm * 32 + lm * 4];
            *(float4*)(a + 4) = *(const float4*)&As[buf][kk][wm * 32 + lm * 4 + 16];
            *(float4*)(b)     = *(const float4*)&Bs[buf][kk][wn * 64 + ln * 4];
            *(float4*)(b + 4) = *(const float4*)&Bs[buf][kk][wn * 64 + ln * 4 + 32];
#pragma unroll
            for (int i = 0; i < 8; i++)
#pragma unroll
                for (int j = 0; j < 8; j++)
                    acc[i][j] = fmaf(a[i], b[j], acc[i][j]);
        }
        if (ch + 1 < nch) {
            buf ^= 1;
            As[buf][colA + 0][rowA] = ra0.x; As[buf][colA + 1][rowA] = ra0.y;
            As[buf][colA + 2][rowA] = ra0.z; As[buf][colA + 3][rowA] = ra0.w;
            As[buf][colA + 0][rowA + 64] = ra1.x; As[buf][colA + 1][rowA + 64] = ra1.y;
            As[buf][colA + 2][rowA + 64] = ra1.z; As[buf][colA + 3][rowA + 64] = ra1.w;
            *(float4*)&Bs[buf][rowB][colB]     = rb0;
            *(float4*)&Bs[buf][rowB + 8][colB] = rb1;
            __syncthreads();
        }
    }

#pragma unroll
    for (int ih = 0; ih < 2; ih++)
#pragma unroll
    for (int i = 0; i < 4; i++) {
        int row = m0 + wm * 32 + ih * 16 + lm * 4 + i;
#pragma unroll
        for (int jh = 0; jh < 2; jh++) {
            int col = n0 + wn * 64 + jh * 32 + ln * 4;
            float* Cp = C + (long)row * N + col;
            float4 v = make_float4(acc[ih*4+i][jh*4+0], acc[ih*4+i][jh*4+1],
                                   acc[ih*4+i][jh*4+2], acc[ih*4+i][jh*4+3]);
            if (flags & 1) {
                const float* bp = bias + col;
                v.x += bp[0]; v.y += bp[1]; v.z += bp[2]; v.w += bp[3];
            }
            *(float4*)Cp = v;
        }
    }
}

// ---------------------------------------------------------------------------
// Base-block fp32 attention (unchanged semantics)
// ---------------------------------------------------------------------------
__global__ __launch_bounds__(256)
void attn_scores_db(const float* __restrict__ Q, const float* __restrict__ Km,
                    float* __restrict__ S)
{
    const int AP = 132;
    __shared__ float Qs[2][16][AP];
    __shared__ float Ks[2][16][AP];

    int tid = threadIdx.x;
    int wid = tid >> 5, lane = tid & 31;
    int wm = wid & 3, wn = wid >> 2;
    int lm = lane & 3, ln = lane >> 2;
    int bh = blockIdx.y;
    int b = bh >> 3, h = bh & 7;
    int q0 = (blockIdx.x >> 2) * 128;
    int s0 = (blockIdx.x & 3) * 128;

    int rowA = tid >> 2, colA = (tid & 3) << 2;

    const float* Qp = Q  + (long)(b * SS + q0 + rowA) * DD + h * KK + colA;
    const float* Kp = Km + (long)(b * SS + s0 + rowA) * DD + h * KK + colA;

    float acc[8][8];
#pragma unroll
    for (int i = 0; i < 8; i++)
#pragma unroll
        for (int j = 0; j < 8; j++) acc[i][j] = 0.f;

    float4 ra0 = *(const float4*)(Qp);
    float4 ra1 = *(const float4*)(Qp + (long)64 * DD);
    float4 rb0 = *(const float4*)(Kp);
    float4 rb1 = *(const float4*)(Kp + (long)64 * DD);
    Qs[0][colA + 0][rowA] = ra0.x; Qs[0][colA + 1][rowA] = ra0.y;
    Qs[0][colA + 2][rowA] = ra0.z; Qs[0][colA + 3][rowA] = ra0.w;
    Qs[0][colA + 0][rowA + 64] = ra1.x; Qs[0][colA + 1][rowA + 64] = ra1.y;
    Qs[0][colA + 2][rowA + 64] = ra1.z; Qs[0][colA + 3][rowA + 64] = ra1.w;
    Ks[0][colA + 0][rowA] = rb0.x; Ks[0][colA + 1][rowA] = rb0.y;
    Ks[0][colA + 2][rowA] = rb0.z; Ks[0][colA + 3][rowA] = rb0.w;
    Ks[0][colA + 0][rowA + 64] = rb1.x; Ks[0][colA + 1][rowA + 64] = rb1.y;
    Ks[0][colA + 2][rowA + 64] = rb1.z; Ks[0][colA + 3][rowA + 64] = rb1.w;
    __syncthreads();

    int buf = 0;
    for (int ch = 0; ch < 4; ch++) {
        if (ch + 1 < 4) {
            const float* Qp2 = Qp + (ch + 1) * 16;
            const float* Kp2 = Kp + (ch + 1) * 16;
            ra0 = *(const float4*)(Qp2);
            ra1 = *(const float4*)(Qp2 + (long)64 * DD);
            rb0 = *(const float4*)(Kp2);
            rb1 = *(const float4*)(Kp2 + (long)64 * DD);
        }
#pragma unroll
        for (int kk = 0; kk < 16; kk++) {
            float a[8], b[8];
            *(float4*)(a)     = *(const float4*)&Qs[buf][kk][wm * 32 + lm * 4];
            *(float4*)(a + 4) = *(const float4*)&Qs[buf][kk][wm * 32 + lm * 4 + 16];
            *(float4*)(b)     = *(const float4*)&Ks[buf][kk][wn * 64 + ln * 4];
            *(float4*)(b + 4) = *(const float4*)&Ks[buf][kk][wn * 64 + ln * 4 + 32];
#pragma unroll
            for (int i = 0; i < 8; i++)
#pragma unroll
                for (int j = 0; j < 8; j++)
                    acc[i][j] = fmaf(a[i], b[j], acc[i][j]);
        }
        if (ch + 1 < 4) {
            buf ^= 1;
            Qs[buf][colA + 0][rowA] = ra0.x; Qs[buf][colA + 1][rowA] = ra0.y;
            Qs[buf][colA + 2][rowA] = ra0.z; Qs[buf][colA + 3][rowA] = ra0.w;
            Qs[buf][colA + 0][rowA + 64] = ra1.x; Qs[buf][colA + 1][rowA + 64] = ra1.y;
            Qs[buf][colA + 2][rowA + 64] = ra1.z; Qs[buf][colA + 3][rowA + 64] = ra1.w;
            Ks[buf][colA + 0][rowA] = rb0.x; Ks[buf][colA + 1][rowA] = rb0.y;
            Ks[buf][colA + 2][rowA] = rb0.z; Ks[buf][colA + 3][rowA] = rb0.w;
            Ks[buf][colA + 0][rowA + 64] = rb1.x; Ks[buf][colA + 1][rowA + 64] = rb1.y;
            Ks[buf][colA + 2][rowA + 64] = rb1.z; Ks[buf][colA + 3][rowA + 64] = rb1.w;
            __syncthreads();
        }
    }

#pragma unroll
    for (int ih = 0; ih < 2; ih++)
#pragma unroll
    for (int i = 0; i < 4; i++) {
        int row = q0 + wm * 32 + ih * 16 + lm * 4 + i;
#pragma unroll
        for (int jh = 0; jh < 2; jh++) {
            int col = s0 + wn * 64 + jh * 32 + ln * 4;
            float4 v = make_float4(acc[ih*4+i][jh*4+0] * 0.125f, acc[ih*4+i][jh*4+1] * 0.125f,
                                   acc[ih*4+i][jh*4+2] * 0.125f, acc[ih*4+i][jh*4+3] * 0.125f);
            *(float4*)&S[((long)bh * SS + row) * SS + col] = v;
        }
    }
}

__global__ void softmax_rows(float* __restrict__ S)
{
    long gw = (long)(blockIdx.x * blockDim.x + threadIdx.x) >> 5;
    int lane = threadIdx.x & 31;
    float4* row = (float4*)(S + gw * SS);

    float4 v[4];
    float mx = -1e30f;
#pragma unroll
    for (int i = 0; i < 4; i++) {
        v[i] = row[lane + 32 * i];
        mx = fmaxf(mx, fmaxf(fmaxf(v[i].x, v[i].y), fmaxf(v[i].z, v[i].w)));
    }
#pragma unroll
    for (int o = 16; o; o >>= 1) mx = fmaxf(mx, __shfl_xor_sync(0xffffffffu, mx, o));

    float sum = 0.f;
#pragma unroll
    for (int i = 0; i < 4; i++) {
        v[i].x = expf(v[i].x - mx); v[i].y = expf(v[i].y - mx);
        v[i].z = expf(v[i].z - mx); v[i].w = expf(v[i].w - mx);
        sum += (v[i].x + v[i].y) + (v[i].z + v[i].w);
    }
#pragma unroll
    for (int o = 16; o; o >>= 1) sum += __shfl_xor_sync(0xffffffffu, sum, o);

    float inv = 1.f / sum;
#pragma unroll
    for (int i = 0; i < 4; i++) {
        v[i].x *= inv; v[i].y *= inv; v[i].z *= inv; v[i].w *= inv;
        row[lane + 32 * i] = v[i];
    }
}

__global__ __launch_bounds__(256)
void attn_av_db(const float* __restrict__ S, const float* __restrict__ V,
                float* __restrict__ O)
{
    const int AP = 132;
    __shared__ float As[2][16][AP];
    __shared__ float Vs[2][16][64];

    int tid = threadIdx.x;
    int wid = tid >> 5, lane = tid & 31;
    int wm = wid & 3, wn = wid >> 2;
    int lm = lane & 3, ln = lane >> 2;
    int bh = blockIdx.y;
    int b = bh >> 3, h = bh & 7;
    int q0 = blockIdx.x * 128;

    int rowA = tid >> 2, colA = (tid & 3) << 2;
    int rowB = tid >> 4, colB = (tid & 15) << 2;

    const float* Sp = S + ((long)bh * SS + q0 + rowA) * SS + colA;
    const float* Vp = V + (long)(b * SS + rowB) * DD + h * KK + colB;

    float acc[8][4];
#pragma unroll
    for (int i = 0; i < 8; i++)
#pragma unroll
        for (int j = 0; j < 4; j++) acc[i][j] = 0.f;

    float4 ra0 = *(const float4*)(Sp);
    float4 ra1 = *(const float4*)(Sp + (long)64 * SS);
    float4 rb0 = *(const float4*)(Vp);
    As[0][colA + 0][rowA] = ra0.x; As[0][colA + 1][rowA] = ra0.y;
    As[0][colA + 2][rowA] = ra0.z; As[0][colA + 3][rowA] = ra0.w;
    As[0][colA + 0][rowA + 64] = ra1.x; As[0][colA + 1][rowA + 64] = ra1.y;
    As[0][colA + 2][rowA + 64] = ra1.z; As[0][colA + 3][rowA + 64] = ra1.w;
    *(float4*)&Vs[0][rowB][colB] = rb0;
    __syncthreads();

    int buf = 0;
    for (int ch = 0; ch < 32; ch++) {
        if (ch + 1 < 32) {
            const float* Sp2 = Sp + (ch + 1) * 16;
            const float* Vp2 = Vp + (long)(ch + 1) * 16 * DD;
            ra0 = *(const float4*)(Sp2);
            ra1 = *(const float4*)(Sp2 + (long)64 * SS);
            rb0 = *(const float4*)(Vp2);
        }
#pragma unroll
        for (int kk = 0; kk < 16; kk++) {
            float a[8], c[4];
            *(float4*)(a)     = *(const float4*)&As[buf][kk][wm * 32 + lm * 4];
            *(float4*)(a + 4) = *(const float4*)&As[buf][kk][wm * 32 + lm * 4 + 16];
            *(float4*)(c)     = *(const float4*)&Vs[buf][kk][wn * 32 + ln * 4];
#pragma unroll
            for (int i = 0; i < 8; i++)
#pragma unroll
                for (int j = 0; j < 4; j++)
                    acc[i][j] = fmaf(a[i], c[j], acc[i][j]);
        }
        if (ch + 1 < 32) {
            buf ^= 1;
            As[buf][colA + 0][rowA] = ra0.x; As[buf][colA + 1][rowA] = ra0.y;
            As[buf][colA + 2][rowA] = ra0.z; As[buf][colA + 3][rowA] = ra0.w;
            As[buf][colA + 0][rowA + 64] = ra1.x; As[buf][colA + 1][rowA + 64] = ra1.y;
            As[buf][colA + 2][rowA + 64] = ra1.z; As[buf][colA + 3][rowA + 64] = ra1.w;
            *(float4*)&Vs[buf][rowB][colB] = rb0;
            __syncthreads();
        }
    }

#pragma unroll
    for (int ih = 0; ih < 2; ih++)
#pragma unroll
    for (int i = 0; i < 4; i++) {
        int row = q0 + wm * 32 + ih * 16 + lm * 4 + i;
        int col = wn * 32 + ln * 4;
        float4 v = make_float4(acc[ih*4+i][0], acc[ih*4+i][1], acc[ih*4+i][2], acc[ih*4+i][3]);
        *(float4*)&O[(long)(b * SS + row) * DD + h * KK + col] = v;
    }
}

// ---------------------------------------------------------------------------
// Misc small kernels
// ---------------------------------------------------------------------------
__global__ void gate_argmax(const float* __restrict__ H,
                            const float* __restrict__ wg,
                            int* __restrict__ idx)
{
    int tok = (blockIdx.x * blockDim.x + threadIdx.x) >> 5;
    int lane = threadIdx.x & 31;
    const float* hrow = H + (size_t)tok * DD;

    float a0 = 0.f, a1 = 0.f, a2 = 0.f, a3 = 0.f;
    for (int d = lane; d < DD; d += 32) {
        float hv = hrow[d];
        float4 w = ((const float4*)wg)[d];
        a0 = fmaf(hv, w.x, a0);
        a1 = fmaf(hv, w.y, a1);
        a2 = fmaf(hv, w.z, a2);
        a3 = fmaf(hv, w.w, a3);
    }
#pragma unroll
    for (int o = 16; o; o >>= 1) {
        a0 += __shfl_xor_sync(0xffffffffu, a0, o);
        a1 += __shfl_xor_sync(0xffffffffu, a1, o);
        a2 += __shfl_xor_sync(0xffffffffu, a2, o);
        a3 += __shfl_xor_sync(0xffffffffu, a3, o);
    }
    if (lane == 0) {
        float g[4] = {a0, a1, a2, a3};
        int best = 0; float bv = g[0];
#pragma unroll
        for (int e = 1; e < 4; e++) if (g[e] > bv) { bv = g[e]; best = e; }
        idx[tok] = best;
    }
}

__global__ void sum_experts(const float* __restrict__ OUTE, float* __restrict__ AGG)
{
    long i = (long)blockIdx.x * blockDim.x + threadIdx.x;
    const float4* p0 = (const float4*)OUTE;
    const long n4 = (long)NT * DD / 4;
    float4 a = p0[i], b = p0[i + n4], c = p0[i + 2 * n4], d = p0[i + 3 * n4];
    float4 r;
    r.x = (a.x + b.x) + (c.x + d.x);
    r.y = (a.y + b.y) + (c.y + d.y);
    r.z = (a.z + b.z) + (c.z + d.z);
    r.w = (a.w + b.w) + (c.w + d.w);
    ((float4*)AGG)[i] = r;
}

__global__ void reduce4_bias(const float* __restrict__ P, const float* __restrict__ b2,
                             float* __restrict__ H)
{
    long i = (long)blockIdx.x * blockDim.x + threadIdx.x;  // float4 units
    const long n4 = (long)NT * DD / 4;
    const float4* p = (const float4*)P;
    float4 a = p[i], b = p[i + n4], c = p[i + 2 * n4], d = p[i + 3 * n4];
    float4 bias = *(const float4*)(b2 + ((i * 4) & (DD - 1)));
    float4 r;
    r.x = (a.x + b.x) + (c.x + d.x) + bias.x;
    r.y = (a.y + b.y) + (c.y + d.y) + bias.y;
    r.z = (a.z + b.z) + (c.z + d.z) + bias.z;
    r.w = (a.w + b.w) + (c.w + d.w) + bias.w;
    ((float4*)H)[i] = r;
}

__device__ __forceinline__ float sigf(float x) { return 1.f / (1.f + expf(-x)); }

__global__ __launch_bounds__(512)
void lstm_scan(const float* __restrict__ Z0, const float* __restrict__ W2,
               float* __restrict__ out)
{
    int b = blockIdx.x;
    int j = threadIdx.x;
    __shared__ float hs[128], cs[128], zs[512];
    if (j < 128) { hs[j] = 0.f; cs[j] = 0.f; }
    __syncthreads();

    for (int t = 0; t < SS; t++) {
        float acc0 = 0.f, acc1 = 0.f, acc2 = 0.f, acc3 = 0.f;
#pragma unroll 8
        for (int u = 0; u < 128; u += 4) {
            acc0 = fmaf(hs[u],     __ldg(&W2[(size_t)(u)     * 512 + j]), acc0);
            acc1 = fmaf(hs[u + 1], __ldg(&W2[(size_t)(u + 1) * 512 + j]), acc1);
            acc2 = fmaf(hs[u + 2], __ldg(&W2[(size_t)(u + 2) * 512 + j]), acc2);
            acc3 = fmaf(hs[u + 3], __ldg(&W2[(size_t)(u + 3) * 512 + j]), acc3);
        }
        float z = Z0[((size_t)(b * SS + t)) * 512 + j] + ((acc0 + acc1) + (acc2 + acc3));
        zs[j] = z;
        __syncthreads();
        if (j < 128) {
            float iv = zs[j], gv = zs[j + 128], fv = zs[j + 256], ov = zs[j + 384];
            float c2 = sigf(fv + 1.f) * cs[j] + sigf(iv) * tanhf(gv);
            float h2 = sigf(ov) * tanhf(c2);
            cs[j] = c2; hs[j] = h2;
            out[((size_t)(b * SS + t)) * LL + j] = h2;
        }
        __syncthreads();
    }
}

__global__ void head_dot(const float* __restrict__ Lh, const float* __restrict__ wd,
                         const float* __restrict__ bd, float* __restrict__ out)
{
    int tok = (blockIdx.x * blockDim.x + threadIdx.x) >> 5;
    int lane = threadIdx.x & 31;
    float4 lv = ((const float4*)(Lh + (size_t)tok * LL))[lane];
    float4 wv = ((const float4*)wd)[lane];
    float acc = lv.x * wv.x + lv.y * wv.y + lv.z * wv.z + lv.w * wv.w;
#pragma unroll
    for (int o = 16; o; o >>= 1) acc += __shfl_xor_sync(0xffffffffu, acc, o);
    if (lane == 0) out[tok] = acc + bd[0];
}

// ---------------------------------------------------------------------------
// Host launcher
// ---------------------------------------------------------------------------
extern "C" void kernel_launch(void* const* d_in, const int* in_sizes, int n_in,
                              void* d_out, int out_size)
{
    const int*   inputs  = (const int*)  d_in[0];
    const float* embed   = (const float*)d_in[1];
    const float* wq      = (const float*)d_in[2];
    const float* wk      = (const float*)d_in[3];
    const float* wv      = (const float*)d_in[4];
    const float* wo      = (const float*)d_in[5];
    const float* w1      = (const float*)d_in[6];
    const float* b1      = (const float*)d_in[7];
    const float* w2      = (const float*)d_in[8];
    const float* b2      = (const float*)d_in[9];
    const float* wg      = (const float*)d_in[10];
    const float* e_embed = (const float*)d_in[11];
    const float* e_wq    = (const float*)d_in[12];
    const float* e_wk    = (const float*)d_in[13];
    const float* e_wv    = (const float*)d_in[14];
    const float* e_wo    = (const float*)d_in[15];
    const float* e_w1    = (const float*)d_in[16];
    const float* e_b1    = (const float*)d_in[17];
    const float* e_w2    = (const float*)d_in[18];
    const float* e_b2    = (const float*)d_in[19];
    const float* a_wq    = (const float*)d_in[20];
    const float* a_wk    = (const float*)d_in[21];
    const float* a_wv    = (const float*)d_in[22];
    const float* a_wo    = (const float*)d_in[23];
    const float* lstm_w  = (const float*)d_in[24];
    const float* lstm_b  = (const float*)d_in[25];
    const float* wd      = (const float*)d_in[26];
    const float* bd      = (const float*)d_in[27];

    float *X, *V, *O, *X2, *T1, *H, *AGG, *Z0, *SC, *LST, *XE, *VE, *OUTE, *SCR, *WQKV;
    __nv_bfloat16 *Qhi, *Qlo, *Khi, *Klo, *VThi, *VTlo, *Phi, *Plo;
    __nv_bfloat16 *ABhi, *ABlo, *CBhi, *CBlo, *WThi, *WTlo;
    int* IDX;
    cudaGetSymbolAddress((void**)&X,    g_X);
    cudaGetSymbolAddress((void**)&V,    g_V);
    cudaGetSymbolAddress((void**)&O,    g_O);
    cudaGetSymbolAddress((void**)&X2,   g_X2);
    cudaGetSymbolAddress((void**)&T1,   g_T1);
    cudaGetSymbolAddress((void**)&H,    g_H);
    cudaGetSymbolAddress((void**)&AGG,  g_AGG);
    cudaGetSymbolAddress((void**)&Z0,   g_Z0);
    cudaGetSymbolAddress((void**)&SC,   g_SC);
    cudaGetSymbolAddress((void**)&LST,  g_LST);
    cudaGetSymbolAddress((void**)&IDX,  g_IDX);
    cudaGetSymbolAddress((void**)&XE,   g_XE);
    cudaGetSymbolAddress((void**)&VE,   g_VE);
    cudaGetSymbolAddress((void**)&OUTE, g_OUTE);
    cudaGetSymbolAddress((void**)&SCR,  g_SCR);
    cudaGetSymbolAddress((void**)&WQKV, g_WQKV);
    cudaGetSymbolAddress((void**)&Qhi,  g_Qhi);
    cudaGetSymbolAddress((void**)&Qlo,  g_Qlo);
    cudaGetSymbolAddress((void**)&Khi,  g_Khi);
    cudaGetSymbolAddress((void**)&Klo,  g_Klo);
    cudaGetSymbolAddress((void**)&VThi, g_VThi);
    cudaGetSymbolAddress((void**)&VTlo, g_VTlo);
    cudaGetSymbolAddress((void**)&Phi,  g_Phi);
    cudaGetSymbolAddress((void**)&Plo,  g_Plo);
    cudaGetSymbolAddress((void**)&ABhi, g_ABhi);
    cudaGetSymbolAddress((void**)&ABlo, g_ABlo);
    cudaGetSymbolAddress((void**)&CBhi, g_CBhi);
    cudaGetSymbolAddress((void**)&CBlo, g_CBlo);
    cudaGetSymbolAddress((void**)&WThi, g_WThi);
    cudaGetSymbolAddress((void**)&WTlo, g_WTlo);

    static bool attr_set = false;
    if (!attr_set) {
        cudaFuncSetAttribute(hgemm_split, cudaFuncAttributeMaxDynamicSharedMemorySize, HG_SMEM);
        cudaFuncSetAttribute(tc_scores,   cudaFuncAttributeMaxDynamicSharedMemorySize, TCS_SMEM);
        cudaFuncSetAttribute(tc_av,       cudaFuncAttributeMaxDynamicSharedMemorySize, TAV_SMEM);
        attr_set = true;
    }

    const long sTOK = (long)NT * DD;
    const long sW   = (long)DD * DD;
    const long sWF  = (long)DD * FF;

    dim3 tb(32, 8);

    // ---------------- weight prep ----------------
    tsplit<<<dim3(16, 16, EE), tb>>>(e_wq, WThi + OFF_EQ, WTlo + OFF_EQ, DD, DD, sW, sW);
    tsplit<<<dim3(16, 16, EE), tb>>>(e_wk, WThi + OFF_EK, WTlo + OFF_EK, DD, DD, sW, sW);
    tsplit<<<dim3(16, 16, EE), tb>>>(e_wv, WThi + OFF_EV, WTlo + OFF_EV, DD, DD, sW, sW);
    tsplit<<<dim3(16, 16, EE), tb>>>(e_wo, WThi + OFF_EO, WTlo + OFF_EO, DD, DD, sW, sW);
    tsplit<<<dim3(64, 16, EE), tb>>>(e_w1, WThi + OFF_E1, WTlo + OFF_E1, DD, FF, sWF, sWF);
    tsplit<<<dim3(16, 64, EE), tb>>>(e_w2, WThi + OFF_E2, WTlo + OFF_E2, FF, DD, sWF, sWF);
    tsplit<<<dim3(16, 16, 1),  tb>>>(a_wq, WThi + OFF_AQ, WTlo + OFF_AQ, DD, DD, 0, 0);
    tsplit<<<dim3(16, 16, 1),  tb>>>(a_wk, WThi + OFF_AK, WTlo + OFF_AK, DD, DD, 0, 0);
    tsplit<<<dim3(16, 16, 1),  tb>>>(a_wv, WThi + OFF_AV, WTlo + OFF_AV, DD, DD, 0, 0);
    tsplit<<<dim3(16, 16, 1),  tb>>>(a_wo, WThi + OFF_AO, WTlo + OFF_AO, DD, DD, 0, 0);
    tsplit<<<dim3(16, 16, 1),  tb>>>(lstm_w, WThi + OFF_LS, WTlo + OFF_LS, DD, DD, 0, 0);
    pack3<<<768, 256>>>(wq, wk, wv, WQKV);

    // ---------------- base block (fp32 — protects routing) ----------------
    embed_gather<<<NT, 128>>>(inputs, embed, X);
    // fused QKV: z=3 -> SCR[0..3*NT*DD)
    sgemm_db<<<dim3(4, 32, 3), 256>>>(X, WQKV, nullptr, SCR, NT, DD, DD, DD, 0,
                                      0, sW, 0, sTOK);
    attn_scores_db<<<dim3(16, 64), 256>>>(SCR, SCR + sTOK, SC);
    softmax_rows<<<4096, 256>>>(SC);
    attn_av_db<<<dim3(4, 64), 256>>>(SC, SCR + 2 * sTOK, O);
    sgemm_db<<<dim3(4, 32, 1), 256>>>(O, wo, nullptr, X2, NT, DD, DD, DD, 0, 0, 0, 0, 0);
    sgemm_db<<<dim3(16, 32, 1), 256>>>(X2, w1, b1, T1, NT, FF, DD, DD, 1, 0, 0, 0, 0);
    // FFN2 split-K (z=4) into SCR partials, then reduce+bias
    sgemm_db<<<dim3(4, 32, 4), 256>>>(T1, w2, nullptr, SCR, NT, DD, 512, FF, 0,
                                      512, (long)512 * DD, 0, sTOK);
    reduce4_bias<<<2048, 256>>>(SCR, b2, H);
    gate_argmax<<<512, 256>>>(H, wg, IDX);

    // ---------------- expert blocks (tensor-core) ----------------
    embed_gather_e<<<dim3(NT, EE), 128>>>(inputs, IDX, e_embed, XE);
    split_bf<<<(EE * NT * DD / 4 + 255) / 256, 256>>>(XE, ABhi, ABlo, (long)EE * NT * DD);
    hgemm_split<<<dim3(4, 32, EE), 256, HG_SMEM>>>(ABhi, ABlo, WThi + OFF_EQ, WTlo + OFF_EQ,
        nullptr, nullptr, Qhi, Qlo, NT, DD, DD, 0, sTOK, sW, 0, sTOK);
    hgemm_split<<<dim3(4, 32, EE), 256, HG_SMEM>>>(ABhi, ABlo, WThi + OFF_EK, WTlo + OFF_EK,
        nullptr, nullptr, Khi, Klo, NT, DD, DD, 0, sTOK, sW, 0, sTOK);
    hgemm_split<<<dim3(4, 32, EE), 256, HG_SMEM>>>(ABhi, ABlo, WThi + OFF_EV, WTlo + OFF_EV,
        nullptr, VE, nullptr, nullptr, NT, DD, DD, 0, sTOK, sW, 0, sTOK);
    vtsplit<<<dim3(16, 2, 64 * EE), tb>>>(VE, VThi, VTlo);
    tc_scores<<<dim3(4, 4, 64 * EE), 256, TCS_SMEM>>>(Qhi, Qlo, Khi, Klo, Phi, Plo);
    softmax_split<<<16384, 256>>>(Phi, Plo);
    tc_av<<<dim3(4, 1, 64 * EE), 256, TAV_SMEM>>>(Phi, Plo, VThi, VTlo, ABhi, ABlo);
    hgemm_split<<<dim3(4, 32, EE), 256, HG_SMEM>>>(ABhi, ABlo, WThi + OFF_EO, WTlo + OFF_EO,
        nullptr, nullptr, CBhi, CBlo, NT, DD, DD, 0, sTOK, sW, 0, sTOK);
    hgemm_split<<<dim3(16, 32, EE), 256, HG_SMEM>>>(CBhi, CBlo, WThi + OFF_E1, WTlo + OFF_E1,
        e_b1, nullptr, ABhi, ABlo, NT, FF, DD, 1, sTOK, sWF, FF, (long)NT * FF);
    hgemm_split<<<dim3(4, 32, EE), 256, HG_SMEM>>>(ABhi, ABlo, WThi + OFF_E2, WTlo + OFF_E2,
        e_b2, OUTE, nullptr, nullptr, NT, DD, FF, 1, (long)NT * FF, sWF, DD, sTOK);
    sum_experts<<<(NT * DD / 4) / 256, 256>>>(OUTE, AGG);

    // ---------------- final attention (tensor-core) ----------------
    split_bf<<<(NT * DD / 4 + 255) / 256, 256>>>(AGG, ABhi, ABlo, (long)NT * DD);
    hgemm_split<<<dim3(4, 32, 1), 256, HG_SMEM>>>(ABhi, ABlo, WThi + OFF_AQ, WTlo + OFF_AQ,
        nullptr, nullptr, Qhi, Qlo, NT, DD, DD, 0, 0, 0, 0, 0);
    hgemm_split<<<dim3(4, 32, 1), 256, HG_SMEM>>>(ABhi, ABlo, WThi + OFF_AK, WTlo + OFF_AK,
        nullptr, nullptr, Khi, Klo, NT, DD, DD, 0, 0, 0, 0, 0);
    hgemm_split<<<dim3(4, 32, 1), 256, HG_SMEM>>>(ABhi, ABlo, WThi + OFF_AV, WTlo + OFF_AV,
        nullptr, V, nullptr, nullptr, NT, DD, DD, 0, 0, 0, 0, 0);
    vtsplit<<<dim3(16, 2, 64), tb>>>(V, VThi, VTlo);
    tc_scores<<<dim3(4, 4, 64), 256, TCS_SMEM>>>(Qhi, Qlo, Khi, Klo, Phi, Plo);
    softmax_split<<<4096, 256>>>(Phi, Plo);
    tc_av<<<dim3(4, 1, 64), 256, TAV_SMEM>>>(Phi, Plo, VThi, VTlo, ABhi, ABlo);
    hgemm_split<<<dim3(4, 32, 1), 256, HG_SMEM>>>(ABhi, ABlo, WThi + OFF_AO, WTlo + OFF_AO,
        nullptr, nullptr, CBhi, CBlo, NT, DD, DD, 0, 0, 0, 0, 0);

    // ---------------- LSTM + head ----------------
    hgemm_split<<<dim3(4, 32, 1), 256, HG_SMEM>>>(CBhi, CBlo, WThi + OFF_LS, WTlo + OFF_LS,
        lstm_b, Z0, nullptr, nullptr, NT, DD, DD, 1, 0, 0, 0, 0);
    lstm_scan<<<BB, 512>>>(Z0, lstm_w + 512 * 512, LST);
    head_dot<<<512, 256>>>(LST, wd, bd, (float*)d_out);
}

// round 12
// speedup vs baseline: 1.0077x; 1.0077x over previous
#include <cuda_runtime.h>
#include <cuda_bf16.h>
#include <cstdint>
#include <cstddef>

// ---------------------------------------------------------------------------
// Problem constants
// ---------------------------------------------------------------------------
#define VV 50257
#define DD 512
#define HH 8
#define KK 64
#define FF 2048
#define EE 4
#define LL 128
#define BB 8
#define SS 512
#define NT 4096   // B*S tokens

// ---------------------------------------------------------------------------
// Scratch (device globals -- no runtime allocation allowed)
// ---------------------------------------------------------------------------
__device__ float g_X  [NT * DD];
__device__ float g_V  [NT * DD];
__device__ float g_O  [NT * DD];
__device__ float g_X2 [NT * DD];
__device__ float g_T1 [NT * FF];
__device__ float g_H  [NT * DD];
__device__ float g_AGG[NT * DD];
__device__ float g_Z0 [NT * DD];
__device__ float g_SC [BB * HH * SS * SS];     // 64 MB (base attention only)
__device__ float g_LST[NT * LL];
__device__ int   g_IDX[NT];
__device__ float g_XE  [EE * NT * DD];
__device__ float g_VE  [EE * NT * DD];
__device__ float g_OUTE[EE * NT * DD];
__device__ float g_SCR [4 * NT * DD];          // base QKV / split-K partials
__device__ float g_WQKV[3 * DD * DD];

// bf16 split buffers
__device__ __nv_bfloat16 g_Qhi[EE * NT * DD];
__device__ __nv_bfloat16 g_Qlo[EE * NT * DD];
__device__ __nv_bfloat16 g_Khi[EE * NT * DD];
__device__ __nv_bfloat16 g_Klo[EE * NT * DD];
__device__ __nv_bfloat16 g_VThi[EE * NT * DD];
__device__ __nv_bfloat16 g_VTlo[EE * NT * DD];
__device__ __nv_bfloat16 g_Phi[(long)EE * BB * HH * SS * SS];
__device__ __nv_bfloat16 g_Plo[(long)EE * BB * HH * SS * SS];
#define ABMAX ((long)EE * NT * FF)
__device__ __nv_bfloat16 g_ABhi[ABMAX];
__device__ __nv_bfloat16 g_ABlo[ABMAX];
__device__ __nv_bfloat16 g_CBhi[ABMAX];
__device__ __nv_bfloat16 g_CBlo[ABMAX];

// transposed+split weights, packed offsets (elements)
#define OFF_EQ 0L
#define OFF_EK 1048576L
#define OFF_EV 2097152L
#define OFF_EO 3145728L
#define OFF_E1 4194304L
#define OFF_E2 8388608L
#define OFF_AQ 12582912L
#define OFF_AK 12845056L
#define OFF_AV 13107200L
#define OFF_AO 13369344L
#define OFF_LS 13631488L
#define WT_TOTAL 13893632L
__device__ __nv_bfloat16 g_WThi[WT_TOTAL];
__device__ __nv_bfloat16 g_WTlo[WT_TOTAL];

// ---------------------------------------------------------------------------
// Embedding gathers
// ---------------------------------------------------------------------------
__global__ void embed_gather(const int* __restrict__ ids,
                             const float* __restrict__ emb,
                             float* __restrict__ X)
{
    int tok = blockIdx.x;
    int id = ids[tok];
    const float4* src = (const float4*)(emb + (size_t)id * DD);
    float4* dst = (float4*)(X + (size_t)tok * DD);
    dst[threadIdx.x] = src[threadIdx.x];
}

__global__ void embed_gather_e(const int* __restrict__ ids,
                               const int* __restrict__ route,
                               const float* __restrict__ emb,
                               float* __restrict__ XE)
{
    int e = blockIdx.y;
    int tok = blockIdx.x;
    int id = (route[tok] == e) ? ids[tok] : 0;
    const float4* src = (const float4*)(emb + ((size_t)e * VV + id) * DD);
    float4* dst = (float4*)(XE + ((size_t)e * NT + tok) * DD);
    dst[threadIdx.x] = src[threadIdx.x];
}

// ---------------------------------------------------------------------------
// Split fp32 -> (bf16 hi, bf16 lo)
// ---------------------------------------------------------------------------
__global__ void split_bf(const float* __restrict__ x,
                         __nv_bfloat16* __restrict__ hi,
                         __nv_bfloat16* __restrict__ lo, long n)
{
    long i = ((long)blockIdx.x * blockDim.x + threadIdx.x) * 4;
    if (i >= n) return;
    float4 v = *(const float4*)(x + i);
    __nv_bfloat16 h0 = __float2bfloat16(v.x);
    __nv_bfloat16 h1 = __float2bfloat16(v.y);
    __nv_bfloat16 h2 = __float2bfloat16(v.z);
    __nv_bfloat16 h3 = __float2bfloat16(v.w);
    *(__nv_bfloat162*)(hi + i)     = __nv_bfloat162(h0, h1);
    *(__nv_bfloat162*)(hi + i + 2) = __nv_bfloat162(h2, h3);
    *(__nv_bfloat162*)(lo + i)     = __nv_bfloat162(
        __float2bfloat16(v.x - __bfloat162float(h0)),
        __float2bfloat16(v.y - __bfloat162float(h1)));
    *(__nv_bfloat162*)(lo + i + 2) = __nv_bfloat162(
        __float2bfloat16(v.z - __bfloat162float(h2)),
        __float2bfloat16(v.w - __bfloat162float(h3)));
}

// ---------------------------------------------------------------------------
// Transpose + split weights: W[Kd,N] (z-strided) -> T[N,Kd] hi/lo
// ---------------------------------------------------------------------------
__global__ void tsplit(const float* __restrict__ W,
                       __nv_bfloat16* __restrict__ Thi,
                       __nv_bfloat16* __restrict__ Tlo,
                       int Kd, int N, long sW, long sT)
{
    __shared__ float t[32][33];
    W   += (long)blockIdx.z * sW;
    Thi += (long)blockIdx.z * sT;
    Tlo += (long)blockIdx.z * sT;
    int n0 = blockIdx.x * 32, k0 = blockIdx.y * 32;
    int tx = threadIdx.x, ty = threadIdx.y;
#pragma unroll
    for (int i = 0; i < 32; i += 8)
        t[ty + i][tx] = W[(long)(k0 + ty + i) * N + n0 + tx];
    __syncthreads();
#pragma unroll
    for (int i = 0; i < 32; i += 8) {
        float v = t[tx][ty + i];
        __nv_bfloat16 h = __float2bfloat16(v);
        long idx = (long)(n0 + ty + i) * Kd + k0 + tx;
        Thi[idx] = h;
        Tlo[idx] = __float2bfloat16(v - __bfloat162float(h));
    }
}

// ---------------------------------------------------------------------------
// Transpose + split V per (e,b,h): V[s, h*64+k] -> VT[z][k][s]
// grid (SS/32, KK/32, Z) ; Z = e*64 + b*8 + h
// ---------------------------------------------------------------------------
__global__ void vtsplit(const float* __restrict__ V,
                        __nv_bfloat16* __restrict__ Thi,
                        __nv_bfloat16* __restrict__ Tlo)
{
    __shared__ float t[32][33];
    int z = blockIdx.z, e = z >> 6, bh = z & 63, b = bh >> 3, h = bh & 7;
    int s0 = blockIdx.x * 32, k0 = blockIdx.y * 32;
    int tx = threadIdx.x, ty = threadIdx.y;
#pragma unroll
    for (int i = 0; i < 32; i += 8)
        t[ty + i][tx] = V[((long)e * NT + b * SS + s0 + ty + i) * DD + h * KK + k0 + tx];
    __syncthreads();
#pragma unroll
    for (int i = 0; i < 32; i += 8) {
        float v = t[tx][ty + i];
        __nv_bfloat16 hh = __float2bfloat16(v);
        long idx = ((long)z * KK + k0 + ty + i) * SS + s0 + tx;
        Thi[idx] = hh;
        Tlo[idx] = __float2bfloat16(v - __bfloat162float(hh));
    }
}

// ---------------------------------------------------------------------------
// Pack wq,wk,wv into one contiguous buffer
// ---------------------------------------------------------------------------
__global__ void pack3(const float* __restrict__ a, const float* __restrict__ b,
                      const float* __restrict__ c, float* __restrict__ dst)
{
    int i = blockIdx.x * 256 + threadIdx.x;                // float4 units
    const int per = DD * DD / 4;
    const float* s = (i < per) ? a : (i < 2 * per) ? b : c;
    int off = i % per;
    ((float4*)dst)[i] = ((const float4*)s)[off];
}

// ---------------------------------------------------------------------------
// MMA helpers
// ---------------------------------------------------------------------------
__device__ __forceinline__ void mma16816(float* c, const uint32_t* a, const uint32_t* b)
{
    asm volatile(
        "mma.sync.aligned.m16n8k16.row.col.f32.bf16.bf16.f32 "
        "{%0,%1,%2,%3}, {%4,%5,%6,%7}, {%8,%9}, {%0,%1,%2,%3};"
        : "+f"(c[0]), "+f"(c[1]), "+f"(c[2]), "+f"(c[3])
        : "r"(a[0]), "r"(a[1]), "r"(a[2]), "r"(a[3]), "r"(b[0]), "r"(b[1]));
}

__device__ __forceinline__ void ldsm4(uint32_t* r, uint32_t addr)
{
    asm volatile("ldmatrix.sync.aligned.m8n8.x4.shared.b16 {%0,%1,%2,%3}, [%4];"
                 : "=r"(r[0]), "=r"(r[1]), "=r"(r[2]), "=r"(r[3]) : "r"(addr));
}

__device__ __forceinline__ void split_store2(__nv_bfloat16* hi, __nv_bfloat16* lo,
                                             float x0, float x1)
{
    __nv_bfloat16 h0 = __float2bfloat16(x0);
    __nv_bfloat16 h1 = __float2bfloat16(x1);
    *(__nv_bfloat162*)hi = __nv_bfloat162(h0, h1);
    *(__nv_bfloat162*)lo = __nv_bfloat162(
        __float2bfloat16(x0 - __bfloat162float(h0)),
        __float2bfloat16(x1 - __bfloat162float(h1)));
}

// ---------------------------------------------------------------------------
// Split-bf16 tensor-core GEMM: C = (Ahi+Alo)[M,K] @ (Bhi+Blo)[N,K]^T
// Outputs: fp32 C (if non-null) and/or split bf16 Chi/Clo (if non-null).
// ---------------------------------------------------------------------------
#define HG_SMEM 81920

__global__ __launch_bounds__(256)
void hgemm_split(const __nv_bfloat16* __restrict__ Ahi0, const __nv_bfloat16* __restrict__ Alo0,
                 const __nv_bfloat16* __restrict__ Bhi0, const __nv_bfloat16* __restrict__ Blo0,
                 const float* __restrict__ bias, float* __restrict__ C,
                 __nv_bfloat16* __restrict__ Chi, __nv_bfloat16* __restrict__ Clo,
                 int M, int N, int Kd, int flags,
                 long sA, long sB, long sBias, long sC)
{
    extern __shared__ char sm[];
    const __nv_bfloat16* gA[2] = { Ahi0 + (long)blockIdx.z * sA, Alo0 + (long)blockIdx.z * sA };
    const __nv_bfloat16* gB[2] = { Bhi0 + (long)blockIdx.z * sB, Blo0 + (long)blockIdx.z * sB };
    if (bias) bias += (long)blockIdx.z * sBias;
    if (C)   C   += (long)blockIdx.z * sC;
    if (Chi) { Chi += (long)blockIdx.z * sC; Clo += (long)blockIdx.z * sC; }

    int tid = threadIdx.x, lane = tid & 31, wid = tid >> 5;
    int m0 = blockIdx.y * 128, n0 = blockIdx.x * 128;
    int m0w = (wid >> 2) * 64, n0w = (wid & 3) * 32;

    int grow = tid >> 1;
    int gseg = (tid & 1) * 16;

    uint32_t smb = (uint32_t)__cvta_generic_to_shared(sm);

    float acc[4][4][4];
#pragma unroll
    for (int i = 0; i < 4; i++)
#pragma unroll
        for (int j = 0; j < 4; j++)
#pragma unroll
            for (int r = 0; r < 4; r++) acc[i][j][r] = 0.f;

    int r16 = lane & 15, kq = lane >> 4;
    uint32_t aoff = (uint32_t)((m0w + r16) * 80 + kq * 16);
    uint32_t boff = (uint32_t)((n0w + r16) * 80 + kq * 16);
    uint32_t soff = (uint32_t)(grow * 80 + gseg * 2);

    int nch = Kd >> 5;

#pragma unroll
    for (int h = 0; h < 2; h++) {
        const uint4* pa = (const uint4*)(gA[h] + (long)(m0 + grow) * Kd + gseg);
        const uint4* pb = (const uint4*)(gB[h] + (long)(n0 + grow) * Kd + gseg);
        uint4 va0 = pa[0], va1 = pa[1];
        uint4 vb0 = pb[0], vb1 = pb[1];
        *(uint4*)(sm + h * 10240 + soff)              = va0;
        *(uint4*)(sm + h * 10240 + soff + 16)         = va1;
        *(uint4*)(sm + 40960 + h * 10240 + soff)      = vb0;
        *(uint4*)(sm + 40960 + h * 10240 + soff + 16) = vb1;
    }
    __syncthreads();

    uint4 pre[2][2][2];
    int buf = 0;
    for (int ch = 0; ch < nch; ch++) {
        if (ch + 1 < nch) {
            long k0 = (long)(ch + 1) * 32;
#pragma unroll
            for (int h = 0; h < 2; h++) {
                const uint4* pa = (const uint4*)(gA[h] + (long)(m0 + grow) * Kd + k0 + gseg);
                const uint4* pb = (const uint4*)(gB[h] + (long)(n0 + grow) * Kd + k0 + gseg);
                pre[0][h][0] = pa[0]; pre[0][h][1] = pa[1];
                pre[1][h][0] = pb[0]; pre[1][h][1] = pb[1];
            }
        }
#pragma unroll
        for (int ks = 0; ks < 2; ks++) {
            uint32_t afr[2][4][4];
            uint32_t bfr[2][4][2];
#pragma unroll
            for (int h = 0; h < 2; h++) {
                uint32_t ab = smb + (buf * 2 + h) * 10240 + aoff + ks * 32;
#pragma unroll
                for (int i = 0; i < 4; i++)
                    ldsm4(afr[h][i], ab + i * 16 * 80);
                uint32_t bb = smb + 40960 + (buf * 2 + h) * 10240 + boff + ks * 32;
#pragma unroll
                for (int j2 = 0; j2 < 2; j2++) {
                    uint32_t t[4];
                    ldsm4(t, bb + j2 * 16 * 80);
                    bfr[h][2 * j2][0]     = t[0]; bfr[h][2 * j2][1]     = t[2];
                    bfr[h][2 * j2 + 1][0] = t[1]; bfr[h][2 * j2 + 1][1] = t[3];
                }
            }
#pragma unroll
            for (int i = 0; i < 4; i++)
#pragma unroll
                for (int j = 0; j < 4; j++) {
                    mma16816(acc[i][j], afr[0][i], bfr[0][j]);
                    mma16816(acc[i][j], afr[0][i], bfr[1][j]);
                    mma16816(acc[i][j], afr[1][i], bfr[0][j]);
                }
        }
        if (ch + 1 < nch) {
            buf ^= 1;
#pragma unroll
            for (int h = 0; h < 2; h++) {
                *(uint4*)(sm + (buf * 2 + h) * 10240 + soff)              = pre[0][h][0];
                *(uint4*)(sm + (buf * 2 + h) * 10240 + soff + 16)         = pre[0][h][1];
                *(uint4*)(sm + 40960 + (buf * 2 + h) * 10240 + soff)      = pre[1][h][0];
                *(uint4*)(sm + 40960 + (buf * 2 + h) * 10240 + soff + 16) = pre[1][h][1];
            }
            __syncthreads();
        }
    }

    int rl = lane >> 2;
    int cl = (lane & 3) * 2;
#pragma unroll
    for (int i = 0; i < 4; i++) {
        int row = m0 + m0w + i * 16 + rl;
#pragma unroll
        for (int j = 0; j < 4; j++) {
            int col = n0 + n0w + j * 8 + cl;
            float x0 = acc[i][j][0], x1 = acc[i][j][1];
            float x2 = acc[i][j][2], x3 = acc[i][j][3];
            if (flags & 1) {
                float b0 = bias[col], b1 = bias[col + 1];
                x0 += b0; x1 += b1; x2 += b0; x3 += b1;
            }
            if (C) {
                *(float2*)(C + (long)row * N + col)       = make_float2(x0, x1);
                *(float2*)(C + (long)(row + 8) * N + col) = make_float2(x2, x3);
            }
            if (Chi) {
                split_store2(Chi + (long)row * N + col, Clo + (long)row * N + col, x0, x1);
                split_store2(Chi + (long)(row + 8) * N + col, Clo + (long)(row + 8) * N + col, x2, x3);
            }
        }
    }
}

// ---------------------------------------------------------------------------
// TC attention scores: P(raw) = (1/8) Q K^T per (e,b,h), split-bf16 in/out.
// grid (4 s-tiles, 4 q-tiles, Z=e*64+bh), 256 threads.
// ---------------------------------------------------------------------------
#define TCS_SMEM (4 * 128 * 72 * 2)

__global__ __launch_bounds__(256)
void tc_scores(const __nv_bfloat16* __restrict__ Qhi, const __nv_bfloat16* __restrict__ Qlo,
               const __nv_bfloat16* __restrict__ Khi, const __nv_bfloat16* __restrict__ Klo,
               __nv_bfloat16* __restrict__ Phi, __nv_bfloat16* __restrict__ Plo)
{
    extern __shared__ char sm[];
    int z = blockIdx.z, e = z >> 6, bh = z & 63, b = bh >> 3, h = bh & 7;
    int q0 = blockIdx.y * 128, s0 = blockIdx.x * 128;
    int tid = threadIdx.x, lane = tid & 31, wid = tid >> 5;

    long qb = ((long)e * NT + b * SS + q0) * DD + h * KK;
    long kb = ((long)e * NT + b * SS + s0) * DD + h * KK;

    int row = tid >> 1, hf = (tid & 1) * 32;
    {
        long ga = qb + (long)row * DD + hf;
        long gk = kb + (long)row * DD + hf;
        char* sp = sm + (row * 72 + hf) * 2;
        // full 32 elems (64 bytes) per thread for each of the 4 operands
#pragma unroll
        for (int u = 0; u < 4; u++) {
            *(uint4*)(sp + u * 16)         = *(const uint4*)(Qhi + ga + u * 8);
            *(uint4*)(sp + 18432 + u * 16) = *(const uint4*)(Qlo + ga + u * 8);
            *(uint4*)(sp + 36864 + u * 16) = *(const uint4*)(Khi + gk + u * 8);
            *(uint4*)(sp + 55296 + u * 16) = *(const uint4*)(Klo + gk + u * 8);
        }
    }
    __syncthreads();

    uint32_t smb = (uint32_t)__cvta_generic_to_shared(sm);
    int m0w = (wid >> 2) * 64, n0w = (wid & 3) * 32;
    int r16 = lane & 15, kq = lane >> 4;

    float acc[4][4][4];
#pragma unroll
    for (int i = 0; i < 4; i++)
#pragma unroll
        for (int j = 0; j < 4; j++)
#pragma unroll
            for (int r = 0; r < 4; r++) acc[i][j][r] = 0.f;

#pragma unroll
    for (int ks = 0; ks < 4; ks++) {
        uint32_t afr[2][4][4], bfr[2][4][2];
#pragma unroll
        for (int hh = 0; hh < 2; hh++) {
            uint32_t ab = smb + hh * 18432 + (m0w + r16) * 144 + kq * 16 + ks * 32;
#pragma unroll
            for (int i = 0; i < 4; i++)
                ldsm4(afr[hh][i], ab + i * 16 * 144);
            uint32_t bb = smb + 36864 + hh * 18432 + (n0w + r16) * 144 + kq * 16 + ks * 32;
#pragma unroll
            for (int j2 = 0; j2 < 2; j2++) {
                uint32_t t[4];
                ldsm4(t, bb + j2 * 16 * 144);
                bfr[hh][2 * j2][0]     = t[0]; bfr[hh][2 * j2][1]     = t[2];
                bfr[hh][2 * j2 + 1][0] = t[1]; bfr[hh][2 * j2 + 1][1] = t[3];
            }
        }
#pragma unroll
        for (int i = 0; i < 4; i++)
#pragma unroll
            for (int j = 0; j < 4; j++) {
                mma16816(acc[i][j], afr[0][i], bfr[0][j]);
                mma16816(acc[i][j], afr[0][i], bfr[1][j]);
                mma16816(acc[i][j], afr[1][i], bfr[0][j]);
            }
    }

    int rl = lane >> 2, cl = (lane & 3) * 2;
    long pb = (long)z * SS * SS;
#pragma unroll
    for (int i = 0; i < 4; i++) {
        int r0 = q0 + m0w + i * 16 + rl;
#pragma unroll
        for (int j = 0; j < 4; j++) {
            int c0 = s0 + n0w + j * 8 + cl;
            long o0 = pb + (long)r0 * SS + c0;
            long o1 = pb + (long)(r0 + 8) * SS + c0;
            split_store2(Phi + o0, Plo + o0, acc[i][j][0] * 0.125f, acc[i][j][1] * 0.125f);
            split_store2(Phi + o1, Plo + o1, acc[i][j][2] * 0.125f, acc[i][j][3] * 0.125f);
        }
    }
}

// ---------------------------------------------------------------------------
// Softmax on split rows (in place): read hi+lo, softmax, write split probs.
// One warp per 512-row.
// ---------------------------------------------------------------------------
__global__ void softmax_split(__nv_bfloat16* __restrict__ Phi,
                              __nv_bfloat16* __restrict__ Plo)
{
    long gw = ((long)blockIdx.x * blockDim.x + threadIdx.x) >> 5;
    int lane = threadIdx.x & 31;
    __nv_bfloat16* ph = Phi + gw * SS + lane * 16;
    __nv_bfloat16* pl = Plo + gw * SS + lane * 16;

    float x[16];
#pragma unroll
    for (int t = 0; t < 8; t++) {
        __nv_bfloat162 a = ((const __nv_bfloat162*)ph)[t];
        __nv_bfloat162 b = ((const __nv_bfloat162*)pl)[t];
        x[2 * t]     = __bfloat162float(a.x) + __bfloat162float(b.x);
        x[2 * t + 1] = __bfloat162float(a.y) + __bfloat162float(b.y);
    }
    float mx = -1e30f;
#pragma unroll
    for (int t = 0; t < 16; t++) mx = fmaxf(mx, x[t]);
#pragma unroll
    for (int o = 16; o; o >>= 1) mx = fmaxf(mx, __shfl_xor_sync(0xffffffffu, mx, o));
    float sum = 0.f;
#pragma unroll
    for (int t = 0; t < 16; t++) { x[t] = expf(x[t] - mx); sum += x[t]; }
#pragma unroll
    for (int o = 16; o; o >>= 1) sum += __shfl_xor_sync(0xffffffffu, sum, o);
    float inv = 1.f / sum;
#pragma unroll
    for (int t = 0; t < 8; t++) {
        float x0 = x[2 * t] * inv, x1 = x[2 * t + 1] * inv;
        __nv_bfloat16 h0 = __float2bfloat16(x0);
        __nv_bfloat16 h1 = __float2bfloat16(x1);
        ((__nv_bfloat162*)ph)[t] = __nv_bfloat162(h0, h1);
        ((__nv_bfloat162*)pl)[t] = __nv_bfloat162(
            __float2bfloat16(x0 - __bfloat162float(h0)),
            __float2bfloat16(x1 - __bfloat162float(h1)));
    }
}

// ---------------------------------------------------------------------------
// TC AV: O[q, k] = sum_s P[q,s] VT[k,s], split in, split out.
// grid (4 q-tiles, 1, Z=e*64+bh), 256 threads.
// ---------------------------------------------------------------------------
#define TAV_SMEM (2 * 128 * 72 * 2 + 2 * 64 * 72 * 2)

__global__ __launch_bounds__(256)
void tc_av(const __nv_bfloat16* __restrict__ Phi, const __nv_bfloat16* __restrict__ Plo,
           const __nv_bfloat16* __restrict__ VThi, const __nv_bfloat16* __restrict__ VTlo,
           __nv_bfloat16* __restrict__ Ohi, __nv_bfloat16* __restrict__ Olo)
{
    extern __shared__ char sm[];
    int z = blockIdx.z, e = z >> 6, bh = z & 63, b = bh >> 3, h = bh & 7;
    int q0 = blockIdx.x * 128;
    int tid = threadIdx.x, lane = tid & 31, wid = tid >> 5;

    long pb = (long)z * SS * SS + (long)q0 * SS;
    long vb = (long)z * KK * SS;

    int m0w = (wid & 3) * 32, n0w = (wid >> 2) * 32;
    int r16 = lane & 15, kq = lane >> 4;

    int arow = tid >> 1, ahalf = (tid & 1) * 32;
    int brow = tid >> 2, bq = (tid & 3) * 16;

    uint32_t smb = (uint32_t)__cvta_generic_to_shared(sm);

    float acc[2][4][4];
#pragma unroll
    for (int i = 0; i < 2; i++)
#pragma unroll
        for (int j = 0; j < 4; j++)
#pragma unroll
            for (int r = 0; r < 4; r++) acc[i][j][r] = 0.f;

    for (int ch = 0; ch < 8; ch++) {
        __syncthreads();
        {
            long ga = pb + (long)arow * SS + ch * 64 + ahalf;
            char* sp = sm + (arow * 72 + ahalf) * 2;
            // full 32 elems (64 bytes) per thread for P hi and lo
#pragma unroll
            for (int u = 0; u < 4; u++) {
                *(uint4*)(sp + u * 16)         = *(const uint4*)(Phi + ga + u * 8);
                *(uint4*)(sp + 18432 + u * 16) = *(const uint4*)(Plo + ga + u * 8);
            }
            long gv = vb + (long)brow * SS + ch * 64 + bq;
            char* sq = sm + 36864 + (brow * 72 + bq) * 2;
            uint4 v;
            v = *(const uint4*)(VThi + gv);     *(uint4*)(sq)             = v;
            v = *(const uint4*)(VThi + gv + 8); *(uint4*)(sq + 16)        = v;
            v = *(const uint4*)(VTlo + gv);     *(uint4*)(sq + 9216)      = v;
            v = *(const uint4*)(VTlo + gv + 8); *(uint4*)(sq + 9216 + 16) = v;
        }
        __syncthreads();

#pragma unroll
        for (int ks = 0; ks < 4; ks++) {
            uint32_t afr[2][2][4], bfr[2][4][2];
#pragma unroll
            for (int hh = 0; hh < 2; hh++) {
                uint32_t ab = smb + hh * 18432 + (m0w + r16) * 144 + kq * 16 + ks * 32;
#pragma unroll
                for (int i = 0; i < 2; i++)
                    ldsm4(afr[hh][i], ab + i * 16 * 144);
                uint32_t bb = smb + 36864 + hh * 9216 + (n0w + r16) * 144 + kq * 16 + ks * 32;
#pragma unroll
                for (int j2 = 0; j2 < 2; j2++) {
                    uint32_t t[4];
                    ldsm4(t, bb + j2 * 16 * 144);
                    bfr[hh][2 * j2][0]     = t[0]; bfr[hh][2 * j2][1]     = t[2];
                    bfr[hh][2 * j2 + 1][0] = t[1]; bfr[hh][2 * j2 + 1][1] = t[3];
                }
            }
#pragma unroll
            for (int i = 0; i < 2; i++)
#pragma unroll
                for (int j = 0; j < 4; j++) {
                    mma16816(acc[i][j], afr[0][i], bfr[0][j]);
                    mma16816(acc[i][j], afr[0][i], bfr[1][j]);
                    mma16816(acc[i][j], afr[1][i], bfr[0][j]);
                }
        }
    }

    int rl = lane >> 2, cl = (lane & 3) * 2;
#pragma unroll
    for (int i = 0; i < 2; i++) {
        int r0 = q0 + m0w + i * 16 + rl;
#pragma unroll
        for (int j = 0; j < 4; j++) {
            int c0 = n0w + j * 8 + cl;
            long o0 = ((long)e * NT + b * SS + r0) * DD + h * KK + c0;
            long o1 = ((long)e * NT + b * SS + r0 + 8) * DD + h * KK + c0;
            split_store2(Ohi + o0, Olo + o0, acc[i][j][0], acc[i][j][1]);
            split_store2(Ohi + o1, Olo + o1, acc[i][j][2], acc[i][j][3]);
        }
    }
}

// ---------------------------------------------------------------------------
// fp32 double-buffered SGEMM (base block), with lda + z-batching
// ---------------------------------------------------------------------------
__global__ __launch_bounds__(256)
void sgemm_db(const float* __restrict__ A, const float* __restrict__ B,
              const float* __restrict__ bias, float* __restrict__ C,
              int M, int N, int Kd, int lda, int flags,
              long sA, long sB, long sBias, long sC)
{
    A += (long)blockIdx.z * sA;
    B += (long)blockIdx.z * sB;
    if (bias) bias += (long)blockIdx.z * sBias;
    C += (long)blockIdx.z * sC;

    const int AP = 132;
    __shared__ float As[2][16][AP];
    __shared__ float Bs[2][16][128];

    int tid = threadIdx.x;
    int wid = tid >> 5, lane = tid & 31;
    int wm = wid & 3, wn = wid >> 2;
    int lm = lane & 3, ln = lane >> 2;
    int m0 = blockIdx.y * 128, n0 = blockIdx.x * 128;

    int rowA = tid >> 2, colA = (tid & 3) << 2;
    int rowB = tid >> 5, colB = lane << 2;

    const float* Ap = A + (long)(m0 + rowA) * lda + colA;
    const float* Bp = B + (long)rowB * N + n0 + colB;

    float acc[8][8];
#pragma unroll
    for (int i = 0; i < 8; i++)
#pragma unroll
        for (int j = 0; j < 8; j++) acc[i][j] = 0.f;

    int nch = Kd >> 4;

    float4 ra0 = *(const float4*)(Ap);
    float4 ra1 = *(const float4*)(Ap + (long)64 * lda);
    float4 rb0 = *(const float4*)(Bp);
    float4 rb1 = *(const float4*)(Bp + (long)8 * N);

    As[0][colA + 0][rowA] = ra0.x; As[0][colA + 1][rowA] = ra0.y;
    As[0][colA + 2][rowA] = ra0.z; As[0][colA + 3][rowA] = ra0.w;
    As[0][colA + 0][rowA + 64] = ra1.x; As[0][colA + 1][rowA + 64] = ra1.y;
    As[0][colA + 2][rowA + 64] = ra1.z; As[0][colA + 3][rowA + 64] = ra1.w;
    *(float4*)&Bs[0][rowB][colB]     = rb0;
    *(float4*)&Bs[0][rowB + 8][colB] = rb1;
    __syncthreads();

    int buf = 0;
    for (int ch = 0; ch < nch; ch++) {
        if (ch + 1 < nch) {
            const float* Ap2 = Ap + (long)(ch + 1) * 16;
            const float* Bp2 = Bp + (long)(ch + 1) * 16 * N;
            ra0 = *(const float4*)(Ap2);
            ra1 = *(const float4*)(Ap2 + (long)64 * lda);
            rb0 = *(const float4*)(Bp2);
            rb1 = *(const float4*)(Bp2 + (long)8 * N);
        }
#pragma unroll
        for (int kk = 0; kk < 16; kk++) {
            float a[8], b[8];
            *(float4*)(a)     = *(const float4*)&As[buf][kk][wm * 32 + lm * 4];
            *(float4*)(a + 4) = *(const float4*)&As[buf][kk][wm * 32 + lm * 4 + 16];
            *(float4*)(b)     = *(const float4*)&Bs[buf][kk][wn * 64 + ln * 4];
            *(float4*)(b + 4) = *(const float4*)&Bs[buf][kk][wn * 64 + ln * 4 + 32];
#pragma unroll
            for (int i = 0; i < 8; i++)
#pragma unroll
                for (int j = 0; j < 8; j++)
                    acc[i][j] = fmaf(a[i], b[j], acc[i][j]);
        }
        if (ch + 1 < nch) {
            buf ^= 1;
            As[buf][colA + 0][rowA] = ra0.x; As[buf][colA + 1][rowA] = ra0.y;
            As[buf][colA + 2][rowA] = ra0.z; As[buf][colA + 3][rowA] = ra0.w;
            As[buf][colA + 0][rowA + 64] = ra1.x; As[buf][colA + 1][rowA + 64] = ra1.y;
            As[buf][colA + 2][rowA + 64] = ra1.z; As[buf][colA + 3][rowA + 64] = ra1.w;
            *(float4*)&Bs[buf][rowB][colB]     = rb0;
            *(float4*)&Bs[buf][rowB + 8][colB] = rb1;
            __syncthreads();
        }
    }

#pragma unroll
    for (int ih = 0; ih < 2; ih++)
#pragma unroll
    for (int i = 0; i < 4; i++) {
        int row = m0 + wm * 32 + ih * 16 + lm * 4 + i;
#pragma unroll
        for (int jh = 0; jh < 2; jh++) {
            int col = n0 + wn * 64 + jh * 32 + ln * 4;
            float* Cp = C + (long)row * N + col;
            float4 v = make_float4(acc[ih*4+i][jh*4+0], acc[ih*4+i][jh*4+1],
                                   acc[ih*4+i][jh*4+2], acc[ih*4+i][jh*4+3]);
            if (flags & 1) {
                const float* bp = bias + col;
                v.x += bp[0]; v.y += bp[1]; v.z += bp[2]; v.w += bp[3];
            }
            *(float4*)Cp = v;
        }
    }
}

// ---------------------------------------------------------------------------
// Base-block fp32 attention (unchanged semantics)
// ---------------------------------------------------------------------------
__global__ __launch_bounds__(256)
void attn_scores_db(const float* __restrict__ Q, const float* __restrict__ Km,
                    float* __restrict__ S)
{
    const int AP = 132;
    __shared__ float Qs[2][16][AP];
    __shared__ float Ks[2][16][AP];

    int tid = threadIdx.x;
    int wid = tid >> 5, lane = tid & 31;
    int wm = wid & 3, wn = wid >> 2;
    int lm = lane & 3, ln = lane >> 2;
    int bh = blockIdx.y;
    int b = bh >> 3, h = bh & 7;
    int q0 = (blockIdx.x >> 2) * 128;
    int s0 = (blockIdx.x & 3) * 128;

    int rowA = tid >> 2, colA = (tid & 3) << 2;

    const float* Qp = Q  + (long)(b * SS + q0 + rowA) * DD + h * KK + colA;
    const float* Kp = Km + (long)(b * SS + s0 + rowA) * DD + h * KK + colA;

    float acc[8][8];
#pragma unroll
    for (int i = 0; i < 8; i++)
#pragma unroll
        for (int j = 0; j < 8; j++) acc[i][j] = 0.f;

    float4 ra0 = *(const float4*)(Qp);
    float4 ra1 = *(const float4*)(Qp + (long)64 * DD);
    float4 rb0 = *(const float4*)(Kp);
    float4 rb1 = *(const float4*)(Kp + (long)64 * DD);
    Qs[0][colA + 0][rowA] = ra0.x; Qs[0][colA + 1][rowA] = ra0.y;
    Qs[0][colA + 2][rowA] = ra0.z; Qs[0][colA + 3][rowA] = ra0.w;
    Qs[0][colA + 0][rowA + 64] = ra1.x; Qs[0][colA + 1][rowA + 64] = ra1.y;
    Qs[0][colA + 2][rowA + 64] = ra1.z; Qs[0][colA + 3][rowA + 64] = ra1.w;
    Ks[0][colA + 0][rowA] = rb0.x; Ks[0][colA + 1][rowA] = rb0.y;
    Ks[0][colA + 2][rowA] = rb0.z; Ks[0][colA + 3][rowA] = rb0.w;
    Ks[0][colA + 0][rowA + 64] = rb1.x; Ks[0][colA + 1][rowA + 64] = rb1.y;
    Ks[0][colA + 2][rowA + 64] = rb1.z; Ks[0][colA + 3][rowA + 64] = rb1.w;
    __syncthreads();

    int buf = 0;
    for (int ch = 0; ch < 4; ch++) {
        if (ch + 1 < 4) {
            const float* Qp2 = Qp + (ch + 1) * 16;
            const float* Kp2 = Kp + (ch + 1) * 16;
            ra0 = *(const float4*)(Qp2);
            ra1 = *(const float4*)(Qp2 + (long)64 * DD);
            rb0 = *(const float4*)(Kp2);
            rb1 = *(const float4*)(Kp2 + (long)64 * DD);
        }
#pragma unroll
        for (int kk = 0; kk < 16; kk++) {
            float a[8], b[8];
            *(float4*)(a)     = *(const float4*)&Qs[buf][kk][wm * 32 + lm * 4];
            *(float4*)(a + 4) = *(const float4*)&Qs[buf][kk][wm * 32 + lm * 4 + 16];
            *(float4*)(b)     = *(const float4*)&Ks[buf][kk][wn * 64 + ln * 4];
            *(float4*)(b + 4) = *(const float4*)&Ks[buf][kk][wn * 64 + ln * 4 + 32];
#pragma unroll
            for (int i = 0; i < 8; i++)
#pragma unroll
                for (int j = 0; j < 8; j++)
                    acc[i][j] = fmaf(a[i], b[j], acc[i][j]);
        }
        if (ch + 1 < 4) {
            buf ^= 1;
            Qs[buf][colA + 0][rowA] = ra0.x; Qs[buf][colA + 1][rowA] = ra0.y;
            Qs[buf][colA + 2][rowA] = ra0.z; Qs[buf][colA + 3][rowA] = ra0.w;
            Qs[buf][colA + 0][rowA + 64] = ra1.x; Qs[buf][colA + 1][rowA + 64] = ra1.y;
            Qs[buf][colA + 2][rowA + 64] = ra1.z; Qs[buf][colA + 3][rowA + 64] = ra1.w;
            Ks[buf][colA + 0][rowA] = rb0.x; Ks[buf][colA + 1][rowA] = rb0.y;
            Ks[buf][colA + 2][rowA] = rb0.z; Ks[buf][colA + 3][rowA] = rb0.w;
            Ks[buf][colA + 0][rowA + 64] = rb1.x; Ks[buf][colA + 1][rowA + 64] = rb1.y;
            Ks[buf][colA + 2][rowA + 64] = rb1.z; Ks[buf][colA + 3][rowA + 64] = rb1.w;
            __syncthreads();
        }
    }

#pragma unroll
    for (int ih = 0; ih < 2; ih++)
#pragma unroll
    for (int i = 0; i < 4; i++) {
        int row = q0 + wm * 32 + ih * 16 + lm * 4 + i;
#pragma unroll
        for (int jh = 0; jh < 2; jh++) {
            int col = s0 + wn * 64 + jh * 32 + ln * 4;
            float4 v = make_float4(acc[ih*4+i][jh*4+0] * 0.125f, acc[ih*4+i][jh*4+1] * 0.125f,
                                   acc[ih*4+i][jh*4+2] * 0.125f, acc[ih*4+i][jh*4+3] * 0.125f);
            *(float4*)&S[((long)bh * SS + row) * SS + col] = v;
        }
    }
}

__global__ void softmax_rows(float* __restrict__ S)
{
    long gw = (long)(blockIdx.x * blockDim.x + threadIdx.x) >> 5;
    int lane = threadIdx.x & 31;
    float4* row = (float4*)(S + gw * SS);

    float4 v[4];
    float mx = -1e30f;
#pragma unroll
    for (int i = 0; i < 4; i++) {
        v[i] = row[lane + 32 * i];
        mx = fmaxf(mx, fmaxf(fmaxf(v[i].x, v[i].y), fmaxf(v[i].z, v[i].w)));
    }
#pragma unroll
    for (int o = 16; o; o >>= 1) mx = fmaxf(mx, __shfl_xor_sync(0xffffffffu, mx, o));

    float sum = 0.f;
#pragma unroll
    for (int i = 0; i < 4; i++) {
        v[i].x = expf(v[i].x - mx); v[i].y = expf(v[i].y - mx);
        v[i].z = expf(v[i].z - mx); v[i].w = expf(v[i].w - mx);
        sum += (v[i].x + v[i].y) + (v[i].z + v[i].w);
    }
#pragma unroll
    for (int o = 16; o; o >>= 1) sum += __shfl_xor_sync(0xffffffffu, sum, o);

    float inv = 1.f / sum;
#pragma unroll
    for (int i = 0; i < 4; i++) {
        v[i].x *= inv; v[i].y *= inv; v[i].z *= inv; v[i].w *= inv;
        row[lane + 32 * i] = v[i];
    }
}

__global__ __launch_bounds__(256)
void attn_av_db(const float* __restrict__ S, const float* __restrict__ V,
                float* __restrict__ O)
{
    const int AP = 132;
    __shared__ float As[2][16][AP];
    __shared__ float Vs[2][16][64];

    int tid = threadIdx.x;
    int wid = tid >> 5, lane = tid & 31;
    int wm = wid & 3, wn = wid >> 2;
    int lm = lane & 3, ln = lane >> 2;
    int bh = blockIdx.y;
    int b = bh >> 3, h = bh & 7;
    int q0 = blockIdx.x * 128;

    int rowA = tid >> 2, colA = (tid & 3) << 2;
    int rowB = tid >> 4, colB = (tid & 15) << 2;

    const float* Sp = S + ((long)bh * SS + q0 + rowA) * SS + colA;
    const float* Vp = V + (long)(b * SS + rowB) * DD + h * KK + colB;

    float acc[8][4];
#pragma unroll
    for (int i = 0; i < 8; i++)
#pragma unroll
        for (int j = 0; j < 4; j++) acc[i][j] = 0.f;

    float4 ra0 = *(const float4*)(Sp);
    float4 ra1 = *(const float4*)(Sp + (long)64 * SS);
    float4 rb0 = *(const float4*)(Vp);
    As[0][colA + 0][rowA] = ra0.x; As[0][colA + 1][rowA] = ra0.y;
    As[0][colA + 2][rowA] = ra0.z; As[0][colA + 3][rowA] = ra0.w;
    As[0][colA + 0][rowA + 64] = ra1.x; As[0][colA + 1][rowA + 64] = ra1.y;
    As[0][colA + 2][rowA + 64] = ra1.z; As[0][colA + 3][rowA + 64] = ra1.w;
    *(float4*)&Vs[0][rowB][colB] = rb0;
    __syncthreads();

    int buf = 0;
    for (int ch = 0; ch < 32; ch++) {
        if (ch + 1 < 32) {
            const float* Sp2 = Sp + (ch + 1) * 16;
            const float* Vp2 = Vp + (long)(ch + 1) * 16 * DD;
            ra0 = *(const float4*)(Sp2);
            ra1 = *(const float4*)(Sp2 + (long)64 * SS);
            rb0 = *(const float4*)(Vp2);
        }
#pragma unroll
        for (int kk = 0; kk < 16; kk++) {
            float a[8], c[4];
            *(float4*)(a)     = *(const float4*)&As[buf][kk][wm * 32 + lm * 4];
            *(float4*)(a + 4) = *(const float4*)&As[buf][kk][wm * 32 + lm * 4 + 16];
            *(float4*)(c)     = *(const float4*)&Vs[buf][kk][wn * 32 + ln * 4];
#pragma unroll
            for (int i = 0; i < 8; i++)
#pragma unroll
                for (int j = 0; j < 4; j++)
                    acc[i][j] = fmaf(a[i], c[j], acc[i][j]);
        }
        if (ch + 1 < 32) {
            buf ^= 1;
            As[buf][colA + 0][rowA] = ra0.x; As[buf][colA + 1][rowA] = ra0.y;
            As[buf][colA + 2][rowA] = ra0.z; As[buf][colA + 3][rowA] = ra0.w;
            As[buf][colA + 0][rowA + 64] = ra1.x; As[buf][colA + 1][rowA + 64] = ra1.y;
            As[buf][colA + 2][rowA + 64] = ra1.z; As[buf][colA + 3][rowA + 64] = ra1.w;
            *(float4*)&Vs[buf][rowB][colB] = rb0;
            __syncthreads();
        }
    }

#pragma unroll
    for (int ih = 0; ih < 2; ih++)
#pragma unroll
    for (int i = 0; i < 4; i++) {
        int row = q0 + wm * 32 + ih * 16 + lm * 4 + i;
        int col = wn * 32 + ln * 4;
        float4 v = make_float4(acc[ih*4+i][0], acc[ih*4+i][1], acc[ih*4+i][2], acc[ih*4+i][3]);
        *(float4*)&O[(long)(b * SS + row) * DD + h * KK + col] = v;
    }
}

// ---------------------------------------------------------------------------
// Misc small kernels
// ---------------------------------------------------------------------------
__global__ void gate_argmax(const float* __restrict__ H,
                            const float* __restrict__ wg,
                            int* __restrict__ idx)
{
    int tok = (blockIdx.x * blockDim.x + threadIdx.x) >> 5;
    int lane = threadIdx.x & 31;
    const float* hrow = H + (size_t)tok * DD;

    float a0 = 0.f, a1 = 0.f, a2 = 0.f, a3 = 0.f;
    for (int d = lane; d < DD; d += 32) {
        float hv = hrow[d];
        float4 w = ((const float4*)wg)[d];
        a0 = fmaf(hv, w.x, a0);
        a1 = fmaf(hv, w.y, a1);
        a2 = fmaf(hv, w.z, a2);
        a3 = fmaf(hv, w.w, a3);
    }
#pragma unroll
    for (int o = 16; o; o >>= 1) {
        a0 += __shfl_xor_sync(0xffffffffu, a0, o);
        a1 += __shfl_xor_sync(0xffffffffu, a1, o);
        a2 += __shfl_xor_sync(0xffffffffu, a2, o);
        a3 += __shfl_xor_sync(0xffffffffu, a3, o);
    }
    if (lane == 0) {
        float g[4] = {a0, a1, a2, a3};
        int best = 0; float bv = g[0];
#pragma unroll
        for (int e = 1; e < 4; e++) if (g[e] > bv) { bv = g[e]; best = e; }
        idx[tok] = best;
    }
}

__global__ void sum_experts(const float* __restrict__ OUTE, float* __restrict__ AGG)
{
    long i = (long)blockIdx.x * blockDim.x + threadIdx.x;
    const float4* p0 = (const float4*)OUTE;
    const long n4 = (long)NT * DD / 4;
    float4 a = p0[i], b = p0[i + n4], c = p0[i + 2 * n4], d = p0[i + 3 * n4];
    float4 r;
    r.x = (a.x + b.x) + (c.x + d.x);
    r.y = (a.y + b.y) + (c.y + d.y);
    r.z = (a.z + b.z) + (c.z + d.z);
    r.w = (a.w + b.w) + (c.w + d.w);
    ((float4*)AGG)[i] = r;
}

__global__ void reduce4_bias(const float* __restrict__ P, const float* __restrict__ b2,
                             float* __restrict__ H)
{
    long i = (long)blockIdx.x * blockDim.x + threadIdx.x;  // float4 units
    const long n4 = (long)NT * DD / 4;
    const float4* p = (const float4*)P;
    float4 a = p[i], b = p[i + n4], c = p[i + 2 * n4], d = p[i + 3 * n4];
    float4 bias = *(const float4*)(b2 + ((i * 4) & (DD - 1)));
    float4 r;
    r.x = (a.x + b.x) + (c.x + d.x) + bias.x;
    r.y = (a.y + b.y) + (c.y + d.y) + bias.y;
    r.z = (a.z + b.z) + (c.z + d.z) + bias.z;
    r.w = (a.w + b.w) + (c.w + d.w) + bias.w;
    ((float4*)H)[i] = r;
}

__device__ __forceinline__ float sigf(float x) { return 1.f / (1.f + expf(-x)); }

__global__ __launch_bounds__(512)
void lstm_scan(const float* __restrict__ Z0, const float* __restrict__ W2,
               float* __restrict__ out)
{
    int b = blockIdx.x;
    int j = threadIdx.x;
    __shared__ float hs[128], cs[128], zs[512];
    if (j < 128) { hs[j] = 0.f; cs[j] = 0.f; }
    __syncthreads();

    for (int t = 0; t < SS; t++) {
        float acc0 = 0.f, acc1 = 0.f, acc2 = 0.f, acc3 = 0.f;
#pragma unroll 8
        for (int u = 0; u < 128; u += 4) {
            acc0 = fmaf(hs[u],     __ldg(&W2[(size_t)(u)     * 512 + j]), acc0);
            acc1 = fmaf(hs[u + 1], __ldg(&W2[(size_t)(u + 1) * 512 + j]), acc1);
            acc2 = fmaf(hs[u + 2], __ldg(&W2[(size_t)(u + 2) * 512 + j]), acc2);
            acc3 = fmaf(hs[u + 3], __ldg(&W2[(size_t)(u + 3) * 512 + j]), acc3);
        }
        float z = Z0[((size_t)(b * SS + t)) * 512 + j] + ((acc0 + acc1) + (acc2 + acc3));
        zs[j] = z;
        __syncthreads();
        if (j < 128) {
            float iv = zs[j], gv = zs[j + 128], fv = zs[j + 256], ov = zs[j + 384];
            float c2 = sigf(fv + 1.f) * cs[j] + sigf(iv) * tanhf(gv);
            float h2 = sigf(ov) * tanhf(c2);
            cs[j] = c2; hs[j] = h2;
            out[((size_t)(b * SS + t)) * LL + j] = h2;
        }
        __syncthreads();
    }
}

__global__ void head_dot(const float* __restrict__ Lh, const float* __restrict__ wd,
                         const float* __restrict__ bd, float* __restrict__ out)
{
    int tok = (blockIdx.x * blockDim.x + threadIdx.x) >> 5;
    int lane = threadIdx.x & 31;
    float4 lv = ((const float4*)(Lh + (size_t)tok * LL))[lane];
    float4 wv = ((const float4*)wd)[lane];
    float acc = lv.x * wv.x + lv.y * wv.y + lv.z * wv.z + lv.w * wv.w;
#pragma unroll
    for (int o = 16; o; o >>= 1) acc += __shfl_xor_sync(0xffffffffu, acc, o);
    if (lane == 0) out[tok] = acc + bd[0];
}

// ---------------------------------------------------------------------------
// Host launcher
// ---------------------------------------------------------------------------
extern "C" void kernel_launch(void* const* d_in, const int* in_sizes, int n_in,
                              void* d_out, int out_size)
{
    const int*   inputs  = (const int*)  d_in[0];
    const float* embed   = (const float*)d_in[1];
    const float* wq      = (const float*)d_in[2];
    const float* wk      = (const float*)d_in[3];
    const float* wv      = (const float*)d_in[4];
    const float* wo      = (const float*)d_in[5];
    const float* w1      = (const float*)d_in[6];
    const float* b1      = (const float*)d_in[7];
    const float* w2      = (const float*)d_in[8];
    const float* b2      = (const float*)d_in[9];
    const float* wg      = (const float*)d_in[10];
    const float* e_embed = (const float*)d_in[11];
    const float* e_wq    = (const float*)d_in[12];
    const float* e_wk    = (const float*)d_in[13];
    const float* e_wv    = (const float*)d_in[14];
    const float* e_wo    = (const float*)d_in[15];
    const float* e_w1    = (const float*)d_in[16];
    const float* e_b1    = (const float*)d_in[17];
    const float* e_w2    = (const float*)d_in[18];
    const float* e_b2    = (const float*)d_in[19];
    const float* a_wq    = (const float*)d_in[20];
    const float* a_wk    = (const float*)d_in[21];
    const float* a_wv    = (const float*)d_in[22];
    const float* a_wo    = (const float*)d_in[23];
    const float* lstm_w  = (const float*)d_in[24];
    const float* lstm_b  = (const float*)d_in[25];
    const float* wd      = (const float*)d_in[26];
    const float* bd      = (const float*)d_in[27];

    float *X, *V, *O, *X2, *T1, *H, *AGG, *Z0, *SC, *LST, *XE, *VE, *OUTE, *SCR, *WQKV;
    __nv_bfloat16 *Qhi, *Qlo, *Khi, *Klo, *VThi, *VTlo, *Phi, *Plo;
    __nv_bfloat16 *ABhi, *ABlo, *CBhi, *CBlo, *WThi, *WTlo;
    int* IDX;
    cudaGetSymbolAddress((void**)&X,    g_X);
    cudaGetSymbolAddress((void**)&V,    g_V);
    cudaGetSymbolAddress((void**)&O,    g_O);
    cudaGetSymbolAddress((void**)&X2,   g_X2);
    cudaGetSymbolAddress((void**)&T1,   g_T1);
    cudaGetSymbolAddress((void**)&H,    g_H);
    cudaGetSymbolAddress((void**)&AGG,  g_AGG);
    cudaGetSymbolAddress((void**)&Z0,   g_Z0);
    cudaGetSymbolAddress((void**)&SC,   g_SC);
    cudaGetSymbolAddress((void**)&LST,  g_LST);
    cudaGetSymbolAddress((void**)&IDX,  g_IDX);
    cudaGetSymbolAddress((void**)&XE,   g_XE);
    cudaGetSymbolAddress((void**)&VE,   g_VE);
    cudaGetSymbolAddress((void**)&OUTE, g_OUTE);
    cudaGetSymbolAddress((void**)&SCR,  g_SCR);
    cudaGetSymbolAddress((void**)&WQKV, g_WQKV);
    cudaGetSymbolAddress((void**)&Qhi,  g_Qhi);
    cudaGetSymbolAddress((void**)&Qlo,  g_Qlo);
    cudaGetSymbolAddress((void**)&Khi,  g_Khi);
    cudaGetSymbolAddress((void**)&Klo,  g_Klo);
    cudaGetSymbolAddress((void**)&VThi, g_VThi);
    cudaGetSymbolAddress((void**)&VTlo, g_VTlo);
    cudaGetSymbolAddress((void**)&Phi,  g_Phi);
    cudaGetSymbolAddress((void**)&Plo,  g_Plo);
    cudaGetSymbolAddress((void**)&ABhi, g_ABhi);
    cudaGetSymbolAddress((void**)&ABlo, g_ABlo);
    cudaGetSymbolAddress((void**)&CBhi, g_CBhi);
    cudaGetSymbolAddress((void**)&CBlo, g_CBlo);
    cudaGetSymbolAddress((void**)&WThi, g_WThi);
    cudaGetSymbolAddress((void**)&WTlo, g_WTlo);

    static bool attr_set = false;
    if (!attr_set) {
        cudaFuncSetAttribute(hgemm_split, cudaFuncAttributeMaxDynamicSharedMemorySize, HG_SMEM);
        cudaFuncSetAttribute(tc_scores,   cudaFuncAttributeMaxDynamicSharedMemorySize, TCS_SMEM);
        cudaFuncSetAttribute(tc_av,       cudaFuncAttributeMaxDynamicSharedMemorySize, TAV_SMEM);
        attr_set = true;
    }

    const long sTOK = (long)NT * DD;
    const long sW   = (long)DD * DD;
    const long sWF  = (long)DD * FF;

    dim3 tb(32, 8);

    // ---------------- weight prep ----------------
    tsplit<<<dim3(16, 16, EE), tb>>>(e_wq, WThi + OFF_EQ, WTlo + OFF_EQ, DD, DD, sW, sW);
    tsplit<<<dim3(16, 16, EE), tb>>>(e_wk, WThi + OFF_EK, WTlo + OFF_EK, DD, DD, sW, sW);
    tsplit<<<dim3(16, 16, EE), tb>>>(e_wv, WThi + OFF_EV, WTlo + OFF_EV, DD, DD, sW, sW);
    tsplit<<<dim3(16, 16, EE), tb>>>(e_wo, WThi + OFF_EO, WTlo + OFF_EO, DD, DD, sW, sW);
    tsplit<<<dim3(64, 16, EE), tb>>>(e_w1, WThi + OFF_E1, WTlo + OFF_E1, DD, FF, sWF, sWF);
    tsplit<<<dim3(16, 64, EE), tb>>>(e_w2, WThi + OFF_E2, WTlo + OFF_E2, FF, DD, sWF, sWF);
    tsplit<<<dim3(16, 16, 1),  tb>>>(a_wq, WThi + OFF_AQ, WTlo + OFF_AQ, DD, DD, 0, 0);
    tsplit<<<dim3(16, 16, 1),  tb>>>(a_wk, WThi + OFF_AK, WTlo + OFF_AK, DD, DD, 0, 0);
    tsplit<<<dim3(16, 16, 1),  tb>>>(a_wv, WThi + OFF_AV, WTlo + OFF_AV, DD, DD, 0, 0);
    tsplit<<<dim3(16, 16, 1),  tb>>>(a_wo, WThi + OFF_AO, WTlo + OFF_AO, DD, DD, 0, 0);
    tsplit<<<dim3(16, 16, 1),  tb>>>(lstm_w, WThi + OFF_LS, WTlo + OFF_LS, DD, DD, 0, 0);
    pack3<<<768, 256>>>(wq, wk, wv, WQKV);

    // ---------------- base block (fp32 — protects routing) ----------------
    embed_gather<<<NT, 128>>>(inputs, embed, X);
    // fused QKV: z=3 -> SCR[0..3*NT*DD)
    sgemm_db<<<dim3(4, 32, 3), 256>>>(X, WQKV, nullptr, SCR, NT, DD, DD, DD, 0,
                                      0, sW, 0, sTOK);
    attn_scores_db<<<dim3(16, 64), 256>>>(SCR, SCR + sTOK, SC);
    softmax_rows<<<4096, 256>>>(SC);
    attn_av_db<<<dim3(4, 64), 256>>>(SC, SCR + 2 * sTOK, O);
    sgemm_db<<<dim3(4, 32, 1), 256>>>(O, wo, nullptr, X2, NT, DD, DD, DD, 0, 0, 0, 0, 0);
    sgemm_db<<<dim3(16, 32, 1), 256>>>(X2, w1, b1, T1, NT, FF, DD, DD, 1, 0, 0, 0, 0);
    // FFN2 split-K (z=4) into SCR partials, then reduce+bias
    sgemm_db<<<dim3(4, 32, 4), 256>>>(T1, w2, nullptr, SCR, NT, DD, 512, FF, 0,
                                      512, (long)512 * DD, 0, sTOK);
    reduce4_bias<<<2048, 256>>>(SCR, b2, H);
    gate_argmax<<<512, 256>>>(H, wg, IDX);

    // ---------------- expert blocks (tensor-core) ----------------
    embed_gather_e<<<dim3(NT, EE), 128>>>(inputs, IDX, e_embed, XE);
    split_bf<<<(EE * NT * DD / 4 + 255) / 256, 256>>>(XE, ABhi, ABlo, (long)EE * NT * DD);
    hgemm_split<<<dim3(4, 32, EE), 256, HG_SMEM>>>(ABhi, ABlo, WThi + OFF_EQ, WTlo + OFF_EQ,
        nullptr, nullptr, Qhi, Qlo, NT, DD, DD, 0, sTOK, sW, 0, sTOK);
    hgemm_split<<<dim3(4, 32, EE), 256, HG_SMEM>>>(ABhi, ABlo, WThi + OFF_EK, WTlo + OFF_EK,
        nullptr, nullptr, Khi, Klo, NT, DD, DD, 0, sTOK, sW, 0, sTOK);
    hgemm_split<<<dim3(4, 32, EE), 256, HG_SMEM>>>(ABhi, ABlo, WThi + OFF_EV, WTlo + OFF_EV,
        nullptr, VE, nullptr, nullptr, NT, DD, DD, 0, sTOK, sW, 0, sTOK);
    vtsplit<<<dim3(16, 2, 64 * EE), tb>>>(VE, VThi, VTlo);
    tc_scores<<<dim3(4, 4, 64 * EE), 256, TCS_SMEM>>>(Qhi, Qlo, Khi, Klo, Phi, Plo);
    softmax_split<<<16384, 256>>>(Phi, Plo);
    tc_av<<<dim3(4, 1, 64 * EE), 256, TAV_SMEM>>>(Phi, Plo, VThi, VTlo, ABhi, ABlo);
    hgemm_split<<<dim3(4, 32, EE), 256, HG_SMEM>>>(ABhi, ABlo, WThi + OFF_EO, WTlo + OFF_EO,
        nullptr, nullptr, CBhi, CBlo, NT, DD, DD, 0, sTOK, sW, 0, sTOK);
    hgemm_split<<<dim3(16, 32, EE), 256, HG_SMEM>>>(CBhi, CBlo, WThi + OFF_E1, WTlo + OFF_E1,
        e_b1, nullptr, ABhi, ABlo, NT, FF, DD, 1, sTOK, sWF, FF, (long)NT * FF);
    hgemm_split<<<dim3(4, 32, EE), 256, HG_SMEM>>>(ABhi, ABlo, WThi + OFF_E2, WTlo + OFF_E2,
        e_b2, OUTE, nullptr, nullptr, NT, DD, FF, 1, (long)NT * FF, sWF, DD, sTOK);
    sum_experts<<<(NT * DD / 4) / 256, 256>>>(OUTE, AGG);

    // ---------------- final attention (tensor-core) ----------------
    split_bf<<<(NT * DD / 4 + 255) / 256, 256>>>(AGG, ABhi, ABlo, (long)NT * DD);
    hgemm_split<<<dim3(4, 32, 1), 256, HG_SMEM>>>(ABhi, ABlo, WThi + OFF_AQ, WTlo + OFF_AQ,
        nullptr, nullptr, Qhi, Qlo, NT, DD, DD, 0, 0, 0, 0, 0);
    hgemm_split<<<dim3(4, 32, 1), 256, HG_SMEM>>>(ABhi, ABlo, WThi + OFF_AK, WTlo + OFF_AK,
        nullptr, nullptr, Khi, Klo, NT, DD, DD, 0, 0, 0, 0, 0);
    hgemm_split<<<dim3(4, 32, 1), 256, HG_SMEM>>>(ABhi, ABlo, WThi + OFF_AV, WTlo + OFF_AV,
        nullptr, V, nullptr, nullptr, NT, DD, DD, 0, 0, 0, 0, 0);
    vtsplit<<<dim3(16, 2, 64), tb>>>(V, VThi, VTlo);
    tc_scores<<<dim3(4, 4, 64), 256, TCS_SMEM>>>(Qhi, Qlo, Khi, Klo, Phi, Plo);
    softmax_split<<<4096, 256>>>(Phi, Plo);
    tc_av<<<dim3(4, 1, 64), 256, TAV_SMEM>>>(Phi, Plo, VThi, VTlo, ABhi, ABlo);
    hgemm_split<<<dim3(4, 32, 1), 256, HG_SMEM>>>(ABhi, ABlo, WThi + OFF_AO, WTlo + OFF_AO,
        nullptr, nullptr, CBhi, CBlo, NT, DD, DD, 0, 0, 0, 0, 0);

    // ---------------- LSTM + head ----------------
    hgemm_split<<<dim3(4, 32, 1), 256, HG_SMEM>>>(CBhi, CBlo, WThi + OFF_LS, WTlo + OFF_LS,
        lstm_b, Z0, nullptr, nullptr, NT, DD, DD, 1, 0, 0, 0, 0);
    lstm_scan<<<BB, 512>>>(Z0, lstm_w + 512 * 512, LST);
    head_dot<<<512, 256>>>(LST, wd, bd, (float*)d_out);
}